// round 8
// baseline (speedup 1.0000x reference)
#include <cuda_runtime.h>
#include <cuda_bf16.h>
#include <cstdint>

#define NC_MAX 1000000
#define NP_MAX 100000
#define DIM 64
#define H 4
#define DQK 8
#define DH 32
#define RPE 9
#define KVW 96
#define SCALE 0.35355339059327373f  // 8^-0.5

#define CH 128                     // children per tile
// per-4-child skew: 16B pad per 4-child group -> conflict-free micro-tile loads
#define XIDX4(child, c) (((child) << 6) + (((child) >> 2) << 2) + (c))
#define XS_FLOATS (CH * 64 + (CH / 4) * 4)     // 8320
#define WSV_FLOATS (64 * 64)                   // 4096
#define KS_FLOATS (CH * 33)                    // 4224
#define DYN_FLOATS (XS_FLOATS + WSV_FLOATS + KS_FLOATS)

// ---------------- packed f32x2 helpers ----------------
__device__ __forceinline__ unsigned long long pk2(float v) {
    unsigned long long r;
    asm("mov.b64 %0, {%1, %1};" : "=l"(r) : "f"(v));
    return r;
}
__device__ __forceinline__ void ffma2(unsigned long long& d, unsigned long long a,
                                      unsigned long long b) {
    asm("fma.rn.f32x2 %0, %1, %2, %0;" : "+l"(d) : "l"(a), "l"(b));
}
__device__ __forceinline__ void addf2(unsigned long long& d, unsigned long long a) {
    asm("add.rn.f32x2 %0, %0, %1;" : "+l"(d) : "l"(a));
}
__device__ __forceinline__ void mulf2(unsigned long long& d, unsigned long long a) {
    asm("mul.rn.f32x2 %0, %0, %1;" : "+l"(d) : "l"(a));
}
__device__ __forceinline__ float2 unpk(unsigned long long v) {
    float2 r;
    asm("mov.b64 {%0, %1}, %2;" : "=f"(r.x), "=f"(r.y) : "l"(v));
    return r;
}

// ---------------- device scratch ----------------
__device__ __align__(16) float g_qp[NP_MAX * DH];
__device__ __align__(16) float g_s[NP_MAX * H];
__device__ int g_idx[NC_MAX];
__device__ int g_is64;

// ---------------- index dtype detection ----------------
__global__ void detect_kernel(const unsigned int* __restrict__ raw, int nc) {
    __shared__ int found;
    if (threadIdx.x == 0) found = 0;
    __syncthreads();
    int limit = nc / 2; if (limit > 2048) limit = 2048;
    for (int i = threadIdx.x; i < limit; i += blockDim.x)
        if (raw[2 * i + 1] != 0u) found = 1;
    __syncthreads();
    if (threadIdx.x == 0) g_is64 = (found == 0) ? 1 : 0;
}

__global__ void cvt_index_kernel(const void* __restrict__ idxp, int nc) {
    int i = blockIdx.x * blockDim.x + threadIdx.x;
    if (i >= nc) return;
    if (g_is64) g_idx[i] = (int)((const long long*)idxp)[i];
    else        g_idx[i] = ((const int*)idxp)[i];
}

// ---------------- parent query projection ----------------
__global__ void __launch_bounds__(256, 2) qp_kernel(
    const float* __restrict__ x_parent, const float* __restrict__ wq,
    const float* __restrict__ bq, int np)
{
    const int t = threadIdx.x & 31;
    const int w = threadIdx.x >> 5;
    __shared__ __align__(16) float xs[8][64];

    float wr[64];
#pragma unroll
    for (int c = 0; c < 64; c++) wr[c] = wq[c * DH + t];
    const float b = bq[t];

    const int warps_total = gridDim.x * 8;
    for (int p = blockIdx.x * 8 + w; p < np; p += warps_total) {
        size_t base = (size_t)p * DIM;
        xs[w][t]      = x_parent[base + t];
        xs[w][t + 32] = x_parent[base + 32 + t];
        __syncwarp();
        float a0 = b, a1 = 0.f, a2 = 0.f, a3 = 0.f;
#pragma unroll
        for (int c = 0; c < 64; c += 4) {
            float4 xv = *(const float4*)&xs[w][c];
            a0 += xv.x * wr[c];
            a1 += xv.y * wr[c + 1];
            a2 += xv.z * wr[c + 2];
            a3 += xv.w * wr[c + 3];
        }
        g_qp[(size_t)p * DH + t] = ((a0 + a1) + (a2 + a3)) * SCALE;
        __syncwarp();
    }
}

// ---------------- fused: K-GEMM + compat/exp + V-GEMM + scatter ----------------
// Tile = 128 children, 256 threads, persistent grid-stride over tiles.
// One x staging feeds both the 32-col K projection and the 64-col V projection.
// out accumulates UNNORMALIZED sum(v*e); g_s accumulates sum(e); a final tiny
// kernel divides out by (s + 1e-16)  [division distributes over segment sum].
__global__ void __launch_bounds__(256, 2) fused_kernel(
    const float* __restrict__ x_child, const float* __restrict__ edge_attr,
    const float* __restrict__ wkv, const float* __restrict__ bkv,
    const float* __restrict__ wk_rpe, const float* __restrict__ bk_rpe,
    const float* __restrict__ wq_rpe, const float* __restrict__ bq_rpe,
    float* __restrict__ out, int nc, int ntiles)
{
    extern __shared__ __align__(16) float dsm[];
    float* xs  = dsm;                         // XS_FLOATS (skewed x tile)
    float* wsv = dsm + XS_FLOATS;             // [64][64] V weights
    float* ks  = wsv + WSV_FLOATS;            // [128][33] k tile

    __shared__ __align__(16) float wsk[64][32];
    __shared__ __align__(16) float wkr_s[RPE][32];
    __shared__ __align__(16) float wqr_s[RPE][32];
    __shared__ __align__(16) float bk_s[32];
    __shared__ __align__(16) float bq_s[32];
    __shared__ __align__(16) float eas[CH][12];
    __shared__ __align__(16) float es4[CH][4];
    __shared__ int pidx[CH];

    const int tid = threadIdx.x;
    const int cg = tid & 7;             // col group
    const int chb = (tid >> 3) * 4;     // 4-children base (0..124)
    const int hh = cg >> 1;             // head for V cols cg*8..+7
    const int xbase = chb * 64 + (chb >> 2) * 4;   // XIDX4(chb, 0)

    // one-time weight staging
    for (int k = tid; k < 64 * 32; k += 256) {
        int c = k >> 5, col = k & 31;
        wsk[c][col] = wkv[c * KVW + col];
    }
    for (int k = tid; k < 64 * 64; k += 256) {
        int c = k >> 6, j = k & 63;
        wsv[c * 64 + j] = wkv[c * KVW + DH + j];
    }
    for (int k = tid; k < RPE * 32; k += 256) {
        wkr_s[0][k] = wk_rpe[k];
        wqr_s[0][k] = wq_rpe[k];
    }
    if (tid < 32) {
        bk_s[tid] = bkv[tid] + bk_rpe[tid];
        bq_s[tid] = bq_rpe[tid];
    }
    const ulonglong2 bva = *(const ulonglong2*)&bkv[DH + cg * 8];
    const ulonglong2 bvb = *(const ulonglong2*)&bkv[DH + cg * 8 + 4];
    __syncthreads();

    for (int tile = blockIdx.x; tile < ntiles; tile += gridDim.x) {
        const int i0 = tile * CH;

        // ---- stage pidx, edge_attr, x ----
        if (tid < CH) {
            int i = i0 + tid;
            pidx[tid] = (i < nc) ? g_idx[i] : 0;
        }
        for (int k = tid; k < CH * RPE; k += 256) {
            int child = k / RPE, r = k - child * RPE;
            int i = i0 + child;
            eas[child][r] = (i < nc) ? edge_attr[(size_t)i * RPE + r] : 0.f;
        }
#pragma unroll
        for (int k = 0; k < 8; k++) {
            int idx = tid + 256 * k;          // 0..2047
            int child = idx >> 4, c4 = idx & 15;
            int i = i0 + child;
            float4 xv = make_float4(0.f, 0.f, 0.f, 0.f);
            if (i < nc) xv = *(const float4*)&x_child[(size_t)i * DIM + c4 * 4];
            *(float4*)&xs[XIDX4(child, c4 * 4)] = xv;
        }
        __syncthreads();

        // ---- K sub-pass: 4 children x 4 cols ----
        {
            unsigned long long acc[4][2];
#pragma unroll
            for (int j = 0; j < 4; j++) { acc[j][0] = 0ull; acc[j][1] = 0ull; }
#pragma unroll
            for (int cc = 0; cc < 64; cc += 4) {
                float4 xv[4];
#pragma unroll
                for (int j = 0; j < 4; j++)
                    xv[j] = *(const float4*)&xs[xbase + j * 64 + cc];
#pragma unroll
                for (int u = 0; u < 4; u++) {
                    ulonglong2 wp = *(const ulonglong2*)&wsk[cc + u][cg * 4];
#pragma unroll
                    for (int j = 0; j < 4; j++) {
                        unsigned long long xd = pk2(((const float*)&xv[j])[u]);
                        ffma2(acc[j][0], xd, wp.x);
                        ffma2(acc[j][1], xd, wp.y);
                    }
                }
            }
#pragma unroll
            for (int r = 0; r < RPE; r++) {
                ulonglong2 wp = *(const ulonglong2*)&wkr_s[r][cg * 4];
#pragma unroll
                for (int j = 0; j < 4; j++) {
                    unsigned long long xd = pk2(eas[chb + j][r]);
                    ffma2(acc[j][0], xd, wp.x);
                    ffma2(acc[j][1], xd, wp.y);
                }
            }
            // write k tile (+bias), stride 33
            const int col = cg * 4;
            const float b0 = bk_s[col], b1 = bk_s[col + 1];
            const float b2 = bk_s[col + 2], b3 = bk_s[col + 3];
#pragma unroll
            for (int j = 0; j < 4; j++) {
                float2 lo = unpk(acc[j][0]);
                float2 hi = unpk(acc[j][1]);
                float* kp = &ks[(chb + j) * 33 + col];
                kp[0] = lo.x + b0; kp[1] = lo.y + b1;
                kp[2] = hi.x + b2; kp[3] = hi.y + b3;
            }
        }

        // ---- V sub-pass: 4 children x 8 cols (kept in regs) ----
        unsigned long long vacc[4][4];
#pragma unroll
        for (int j = 0; j < 4; j++) {
            vacc[j][0] = bva.x; vacc[j][1] = bva.y;
            vacc[j][2] = bvb.x; vacc[j][3] = bvb.y;
        }
#pragma unroll
        for (int cc = 0; cc < 64; cc += 4) {
            float4 xv[4];
#pragma unroll
            for (int j = 0; j < 4; j++)
                xv[j] = *(const float4*)&xs[xbase + j * 64 + cc];
#pragma unroll
            for (int u = 0; u < 4; u++) {
                ulonglong2 wpa = *(const ulonglong2*)&wsv[(cc + u) * 64 + cg * 8];
                ulonglong2 wpb = *(const ulonglong2*)&wsv[(cc + u) * 64 + cg * 8 + 4];
#pragma unroll
                for (int j = 0; j < 4; j++) {
                    unsigned long long xd = pk2(((const float*)&xv[j])[u]);
                    ffma2(vacc[j][0], xd, wpa.x);
                    ffma2(vacc[j][1], xd, wpa.y);
                    ffma2(vacc[j][2], xd, wpb.x);
                    ffma2(vacc[j][3], xd, wpb.y);
                }
            }
        }
        __syncthreads();   // ks + eas stable; vacc in regs

        // ---- epilogue-e: 256 threads = 128 children x 2 halves ----
        {
            const int child = tid >> 1;
            const int half = tid & 1;
            const int i = i0 + child;
            if (i < nc) {
                const int p = pidx[child];
                const int col0 = half * 16;
                unsigned long long q[8];
                const unsigned long long* qpv =
                    (const unsigned long long*)&g_qp[(size_t)p * DH + col0];
                const unsigned long long* bqp =
                    (const unsigned long long*)&bq_s[col0];
#pragma unroll
                for (int j = 0; j < 8; j++) { q[j] = qpv[j]; addf2(q[j], bqp[j]); }
#pragma unroll
                for (int r = 0; r < RPE; r++) {
                    unsigned long long ed = pk2(eas[child][r]);
                    const unsigned long long* wqp =
                        (const unsigned long long*)&wqr_s[r][col0];
#pragma unroll
                    for (int j = 0; j < 8; j++) ffma2(q[j], ed, wqp[j]);
                }
                const float* krow = &ks[child * 33 + col0];
                float c0 = 0.f, c1 = 0.f;
#pragma unroll
                for (int j = 0; j < 4; j++) {
                    float2 qq = unpk(q[j]);
                    c0 += qq.x * krow[2 * j] + qq.y * krow[2 * j + 1];
                }
#pragma unroll
                for (int j = 4; j < 8; j++) {
                    float2 qq = unpk(q[j]);
                    c1 += qq.x * krow[2 * j] + qq.y * krow[2 * j + 1];
                }
                es4[child][half * 2 + 0] = __expf(c0);
                es4[child][half * 2 + 1] = __expf(c1);
            }
        }
        __syncthreads();

        // ---- scale v by e and scatter (unnormalized) ----
#pragma unroll
        for (int j = 0; j < 4; j++) {
            if (i0 + chb + j < nc) {
                unsigned long long ed = pk2(es4[chb + j][hh]);
                mulf2(vacc[j][0], ed); mulf2(vacc[j][1], ed);
                mulf2(vacc[j][2], ed); mulf2(vacc[j][3], ed);
                float2 r0 = unpk(vacc[j][0]), r1 = unpk(vacc[j][1]);
                float2 r2 = unpk(vacc[j][2]), r3 = unpk(vacc[j][3]);
                float* dst = out + (size_t)pidx[chb + j] * DIM + cg * 8;
                asm volatile("red.global.add.v4.f32 [%0], {%1,%2,%3,%4};"
                             :: "l"(dst), "f"(r0.x), "f"(r0.y), "f"(r1.x), "f"(r1.y)
                             : "memory");
                asm volatile("red.global.add.v4.f32 [%0], {%1,%2,%3,%4};"
                             :: "l"(dst + 4), "f"(r2.x), "f"(r2.y), "f"(r3.x), "f"(r3.y)
                             : "memory");
            }
        }
        // segment sums of e
        if (tid < CH) {
            int i = i0 + tid;
            if (i < nc) {
                float4 e4 = *(const float4*)&es4[tid][0];
                asm volatile("red.global.add.v4.f32 [%0], {%1,%2,%3,%4};"
                             :: "l"(g_s + (size_t)pidx[tid] * H),
                                "f"(e4.x), "f"(e4.y), "f"(e4.z), "f"(e4.w) : "memory");
            }
        }
        __syncthreads();   // protect shared buffers before next staging
    }
}

// ---------------- final normalize: out[p][j] /= (s[p][j>>4] + 1e-16) ----------------
__global__ void norm_kernel(float* __restrict__ out, int np) {
    int idx = blockIdx.x * blockDim.x + threadIdx.x;   // np*16 float4 groups
    if (idx >= np * 16) return;
    int p = idx >> 4, grp = idx & 15;
    float s = g_s[p * H + (grp >> 2)];
    float inv = 1.0f / (s + 1e-16f);
    float4 v = *(const float4*)&out[(size_t)p * DIM + grp * 4];
    v.x *= inv; v.y *= inv; v.z *= inv; v.w *= inv;
    *(float4*)&out[(size_t)p * DIM + grp * 4] = v;
}

// ---------------- launch ----------------
extern "C" void kernel_launch(void* const* d_in, const int* in_sizes, int n_in,
                              void* d_out, int out_size) {
    const float* x_child   = (const float*)d_in[0];
    const float* x_parent  = (const float*)d_in[1];
    const void*  index     = d_in[2];
    const float* edge_attr = (const float*)d_in[3];
    const float* wq        = (const float*)d_in[4];
    const float* bq        = (const float*)d_in[5];
    const float* wkv       = (const float*)d_in[6];
    const float* bkv       = (const float*)d_in[7];
    const float* wk_rpe    = (const float*)d_in[8];
    const float* bk_rpe    = (const float*)d_in[9];
    const float* wq_rpe    = (const float*)d_in[10];
    const float* bq_rpe    = (const float*)d_in[11];
    float* out = (float*)d_out;

    const int nc = in_sizes[0] / DIM;
    const int np = in_sizes[1] / DIM;

    const int DYN_BYTES = DYN_FLOATS * (int)sizeof(float);   // ~65KB
    static int attr_done = 0;
    if (!attr_done) {
        cudaFuncSetAttribute(fused_kernel,
                             cudaFuncAttributeMaxDynamicSharedMemorySize, DYN_BYTES);
        attr_done = 1;
    }

    cudaMemsetAsync(d_out, 0, (size_t)out_size * sizeof(float));
    void* s_addr = nullptr;
    cudaGetSymbolAddress(&s_addr, g_s);
    cudaMemsetAsync(s_addr, 0, (size_t)np * H * sizeof(float));

    detect_kernel<<<1, 256>>>((const unsigned int*)index, nc);
    cvt_index_kernel<<<(nc + 255) / 256, 256>>>(index, nc);

    qp_kernel<<<208, 256>>>(x_parent, wq, bq, np);

    const int ntiles = (nc + CH - 1) / CH;
    fused_kernel<<<296, 256, DYN_BYTES>>>(x_child, edge_attr, wkv, bkv,
                                          wk_rpe, bk_rpe, wq_rpe, bq_rpe,
                                          out, nc, ntiles);

    norm_kernel<<<(np * 16 + 255) / 256, 256>>>(out, np);
}

// round 9
// speedup vs baseline: 1.5094x; 1.5094x over previous
#include <cuda_runtime.h>
#include <cuda_bf16.h>
#include <cstdint>

#define NC_MAX 1000000
#define NP_MAX 100000
#define DIM 64
#define H 4
#define DQK 8
#define DH 32
#define RPE 9
#define KVW 96
#define SCALE 0.35355339059327373f  // 8^-0.5

// Skewed x-tile index: 16B pad per 8-child group -> conflict-free micro-tile loads
#define XIDX(child, c) (((child) << 6) + (((child) >> 3) << 2) + (c))
#define XS_FLOATS (256 * 64 + 32 * 4)

// ---------------- packed f32x2 helpers ----------------
__device__ __forceinline__ unsigned long long pk2(float v) {
    unsigned long long r;
    asm("mov.b64 %0, {%1, %1};" : "=l"(r) : "f"(v));
    return r;
}
__device__ __forceinline__ void ffma2(unsigned long long& d, unsigned long long a,
                                      unsigned long long b) {
    asm("fma.rn.f32x2 %0, %1, %2, %0;" : "+l"(d) : "l"(a), "l"(b));
}
__device__ __forceinline__ void addf2(unsigned long long& d, unsigned long long a) {
    asm("add.rn.f32x2 %0, %0, %1;" : "+l"(d) : "l"(a));
}
__device__ __forceinline__ void mulf2(unsigned long long& d, unsigned long long a) {
    asm("mul.rn.f32x2 %0, %0, %1;" : "+l"(d) : "l"(a));
}
__device__ __forceinline__ float2 unpk(unsigned long long v) {
    float2 r;
    asm("mov.b64 {%0, %1}, %2;" : "=f"(r.x), "=f"(r.y) : "l"(v));
    return r;
}

// ---------------- device scratch ----------------
__device__ __align__(16) float g_qp[NP_MAX * DH];
__device__ __align__(16) float g_e[NC_MAX * H];
__device__ __align__(16) float g_s[NP_MAX * H];
__device__ int g_idx[NC_MAX];
__device__ int g_is64;

// ---------------- index dtype detection ----------------
__global__ void detect_kernel(const unsigned int* __restrict__ raw, int nc) {
    __shared__ int found;
    if (threadIdx.x == 0) found = 0;
    __syncthreads();
    int limit = nc / 2; if (limit > 2048) limit = 2048;
    for (int i = threadIdx.x; i < limit; i += blockDim.x)
        if (raw[2 * i + 1] != 0u) found = 1;
    __syncthreads();
    if (threadIdx.x == 0) g_is64 = (found == 0) ? 1 : 0;
}

__global__ void cvt_index_kernel(const void* __restrict__ idxp, int nc) {
    int i = blockIdx.x * blockDim.x + threadIdx.x;
    if (i >= nc) return;
    if (g_is64) g_idx[i] = (int)((const long long*)idxp)[i];
    else        g_idx[i] = ((const int*)idxp)[i];
}

// ---------------- parent query projection ----------------
__global__ void __launch_bounds__(256, 2) qp_kernel(
    const float* __restrict__ x_parent, const float* __restrict__ wq,
    const float* __restrict__ bq, int np)
{
    const int t = threadIdx.x & 31;
    const int w = threadIdx.x >> 5;
    __shared__ __align__(16) float xs[8][64];

    float wr[64];
#pragma unroll
    for (int c = 0; c < 64; c++) wr[c] = wq[c * DH + t];
    const float b = bq[t];

    const int warps_total = gridDim.x * 8;
    for (int p = blockIdx.x * 8 + w; p < np; p += warps_total) {
        size_t base = (size_t)p * DIM;
        xs[w][t]      = x_parent[base + t];
        xs[w][t + 32] = x_parent[base + 32 + t];
        __syncwarp();
        float a0 = b, a1 = 0.f, a2 = 0.f, a3 = 0.f;
#pragma unroll
        for (int c = 0; c < 64; c += 4) {
            float4 xv = *(const float4*)&xs[w][c];
            a0 += xv.x * wr[c];
            a1 += xv.y * wr[c + 1];
            a2 += xv.z * wr[c + 2];
            a3 += xv.w * wr[c + 3];
        }
        g_qp[(size_t)p * DH + t] = ((a0 + a1) + (a2 + a3)) * SCALE;
        __syncwarp();
    }
}

// ---------------- compat: 8x4 micro-tile K-GEMM + epilogue (round-6 proven) ----------------
__global__ void __launch_bounds__(256, 2) compat_kernel(
    const float* __restrict__ x_child, const float* __restrict__ edge_attr,
    const float* __restrict__ wkv, const float* __restrict__ bkv,
    const float* __restrict__ wk_rpe, const float* __restrict__ bk_rpe,
    const float* __restrict__ wq_rpe, const float* __restrict__ bq_rpe,
    int nc, int ntiles)
{
    extern __shared__ __align__(16) float xs[];    // XS_FLOATS; reused as ks[256*33]
    __shared__ __align__(16) float ws[64][32];
    __shared__ __align__(16) float wkr_s[RPE][32];
    __shared__ __align__(16) float wqr_s[RPE][32];
    __shared__ __align__(16) float bk_s[32];
    __shared__ __align__(16) float bq_s[32];
    __shared__ __align__(16) float eas[256][12];
    __shared__ __align__(16) float es4[256][4];
    __shared__ int pidx[256];

    const int tid = threadIdx.x;
    const int cg = tid & 7;            // col group: cols cg*4..+3
    const int chb = (tid >> 3) * 8;    // child base: 8 children

    for (int k = tid; k < 64 * 32; k += 256) {
        int c = k >> 5, col = k & 31;
        ws[c][col] = wkv[c * KVW + col];
    }
    for (int k = tid; k < RPE * 32; k += 256) {
        wkr_s[0][k] = wk_rpe[k];
        wqr_s[0][k] = wq_rpe[k];
    }
    if (tid < 32) {
        bk_s[tid] = bkv[tid] + bk_rpe[tid];
        bq_s[tid] = bq_rpe[tid];
    }
    __syncthreads();

    float* ks = xs;

    for (int tile = blockIdx.x; tile < ntiles; tile += gridDim.x) {
        const int i0 = tile * 256;

        {
            int i = i0 + tid;
            pidx[tid] = (i < nc) ? g_idx[i] : 0;
        }
        for (int k = tid; k < 256 * RPE; k += 256) {
            int child = k / RPE, r = k - child * RPE;
            int i = i0 + child;
            eas[child][r] = (i < nc) ? edge_attr[(size_t)i * RPE + r] : 0.f;
        }
#pragma unroll
        for (int k = 0; k < 16; k++) {
            int idx = tid + 256 * k;           // 0..4095
            int child = idx >> 4, c4 = idx & 15;
            int i = i0 + child;
            float4 xv = make_float4(0.f, 0.f, 0.f, 0.f);
            if (i < nc) xv = *(const float4*)&x_child[(size_t)i * DIM + c4 * 4];
            *(float4*)&xs[XIDX(child, c4 * 4)] = xv;
        }
        __syncthreads();

        const int xbase = XIDX(chb, 0);
        unsigned long long acc[8][2];
#pragma unroll
        for (int j = 0; j < 8; j++) { acc[j][0] = 0ull; acc[j][1] = 0ull; }
#pragma unroll
        for (int cc = 0; cc < 64; cc += 4) {
            float4 xv[8];
#pragma unroll
            for (int j = 0; j < 8; j++)
                xv[j] = *(const float4*)&xs[xbase + j * 64 + cc];
#pragma unroll
            for (int u = 0; u < 4; u++) {
                ulonglong2 wp = *(const ulonglong2*)&ws[cc + u][cg * 4];
#pragma unroll
                for (int j = 0; j < 8; j++) {
                    unsigned long long xd = pk2(((const float*)&xv[j])[u]);
                    ffma2(acc[j][0], xd, wp.x);
                    ffma2(acc[j][1], xd, wp.y);
                }
            }
        }
#pragma unroll
        for (int r = 0; r < RPE; r++) {
            ulonglong2 wp = *(const ulonglong2*)&wkr_s[r][cg * 4];
#pragma unroll
            for (int j = 0; j < 8; j++) {
                unsigned long long xd = pk2(eas[chb + j][r]);
                ffma2(acc[j][0], xd, wp.x);
                ffma2(acc[j][1], xd, wp.y);
            }
        }
        __syncthreads();

        {
            const int col = cg * 4;
            const float b0 = bk_s[col], b1 = bk_s[col + 1];
            const float b2 = bk_s[col + 2], b3 = bk_s[col + 3];
#pragma unroll
            for (int j = 0; j < 8; j++) {
                float2 lo = unpk(acc[j][0]);
                float2 hi = unpk(acc[j][1]);
                float* kp = &ks[(chb + j) * 33 + col];
                kp[0] = lo.x + b0; kp[1] = lo.y + b1;
                kp[2] = hi.x + b2; kp[3] = hi.y + b3;
            }
        }
        __syncthreads();

#pragma unroll
        for (int uu = 0; uu < 2; uu++) {
            const int unit = tid + uu * 256;
            const int child = unit >> 1;
            const int half = unit & 1;
            const int i = i0 + child;
            if (i < nc) {
                const int p = pidx[child];
                const int col0 = half * 16;
                unsigned long long q[8];
                const unsigned long long* qpv =
                    (const unsigned long long*)&g_qp[(size_t)p * DH + col0];
                const unsigned long long* bqp =
                    (const unsigned long long*)&bq_s[col0];
#pragma unroll
                for (int j = 0; j < 8; j++) { q[j] = qpv[j]; addf2(q[j], bqp[j]); }
#pragma unroll
                for (int r = 0; r < RPE; r++) {
                    unsigned long long ed = pk2(eas[child][r]);
                    const unsigned long long* wqp =
                        (const unsigned long long*)&wqr_s[r][col0];
#pragma unroll
                    for (int j = 0; j < 8; j++) ffma2(q[j], ed, wqp[j]);
                }
                const float* krow = &ks[child * 33 + col0];
                float c0 = 0.f, c1 = 0.f;
#pragma unroll
                for (int j = 0; j < 4; j++) {
                    float2 qq = unpk(q[j]);
                    c0 += qq.x * krow[2 * j] + qq.y * krow[2 * j + 1];
                }
#pragma unroll
                for (int j = 4; j < 8; j++) {
                    float2 qq = unpk(q[j]);
                    c1 += qq.x * krow[2 * j] + qq.y * krow[2 * j + 1];
                }
                es4[child][half * 2 + 0] = __expf(c0);
                es4[child][half * 2 + 1] = __expf(c1);
            }
        }
        __syncthreads();

        {
            int i = i0 + tid;
            if (i < nc) {
                float4 e4 = *(const float4*)&es4[tid][0];
                *(float4*)&g_e[(size_t)i * H] = e4;
                asm volatile("red.global.add.v4.f32 [%0], {%1,%2,%3,%4};"
                             :: "l"(g_s + (size_t)pidx[tid] * H),
                                "f"(e4.x), "f"(e4.y), "f"(e4.z), "f"(e4.w) : "memory");
            }
        }
        __syncthreads();
    }
}

// ---------------- vout: 8x8 micro-tile V-GEMM, register scatter (unnormalized) ----------------
__global__ void __launch_bounds__(256, 2) vout_kernel(
    const float* __restrict__ x_child, const float* __restrict__ wkv,
    const float* __restrict__ bkv, float* __restrict__ out,
    int nc, int ntiles)
{
    extern __shared__ __align__(16) float xs[];    // XS_FLOATS
    __shared__ __align__(16) float ws[64][64];
    __shared__ __align__(16) float e_s[256][4];    // raw exp(compat)
    __shared__ int pidx[256];

    const int tid = threadIdx.x;
    const int cg = tid & 7;           // cols cg*8..+7 (within one head)
    const int chb = (tid >> 3) * 8;   // children chb..+7
    const int hh = cg >> 1;           // head of this thread's 8 cols

    for (int k = tid; k < 64 * 64; k += 256) {
        int c = k >> 6, j = k & 63;
        ws[c][j] = wkv[c * KVW + DH + j];
    }
    const ulonglong2 bva = *(const ulonglong2*)&bkv[DH + cg * 8];
    const ulonglong2 bvb = *(const ulonglong2*)&bkv[DH + cg * 8 + 4];
    __syncthreads();

    for (int tile = blockIdx.x; tile < ntiles; tile += gridDim.x) {
        const int i0 = tile * 256;

        // stage raw e (coalesced) + pidx
#pragma unroll
        for (int k = 0; k < 4; k++) {
            int idx = tid + 256 * k;          // 0..1023
            int child = idx >> 2, h = idx & 3;
            int i = i0 + child;
            float ev = 0.f; int p = 0;
            if (i < nc) {
                p = g_idx[i];
                ev = g_e[(size_t)i * H + h];
            }
            e_s[child][h] = ev;
            if (h == 0) pidx[child] = p;
        }
#pragma unroll
        for (int k = 0; k < 16; k++) {
            int idx = tid + 256 * k;
            int child = idx >> 4, c4 = idx & 15;
            int i = i0 + child;
            float4 xv = make_float4(0.f, 0.f, 0.f, 0.f);
            if (i < nc) xv = *(const float4*)&x_child[(size_t)i * DIM + c4 * 4];
            *(float4*)&xs[XIDX(child, c4 * 4)] = xv;
        }
        __syncthreads();

        // 8 children x 8 cols micro-tile
        const int xbase = XIDX(chb, 0);
        unsigned long long acc[8][4];
#pragma unroll
        for (int j = 0; j < 8; j++) {
            acc[j][0] = bva.x; acc[j][1] = bva.y;
            acc[j][2] = bvb.x; acc[j][3] = bvb.y;
        }
#pragma unroll
        for (int cc = 0; cc < 64; cc += 4) {
            float4 xv[8];
#pragma unroll
            for (int j = 0; j < 8; j++)
                xv[j] = *(const float4*)&xs[xbase + j * 64 + cc];
#pragma unroll
            for (int u = 0; u < 4; u++) {
                ulonglong2 wpa = *(const ulonglong2*)&ws[cc + u][cg * 8];
                ulonglong2 wpb = *(const ulonglong2*)&ws[cc + u][cg * 8 + 4];
#pragma unroll
                for (int j = 0; j < 8; j++) {
                    unsigned long long xd = pk2(((const float*)&xv[j])[u]);
                    ffma2(acc[j][0], xd, wpa.x);
                    ffma2(acc[j][1], xd, wpa.y);
                    ffma2(acc[j][2], xd, wpb.x);
                    ffma2(acc[j][3], xd, wpb.y);
                }
            }
        }

        // scale by raw e, scatter unnormalized straight from registers
#pragma unroll
        for (int j = 0; j < 8; j++) {
            if (i0 + chb + j < nc) {
                unsigned long long ed = pk2(e_s[chb + j][hh]);
                mulf2(acc[j][0], ed); mulf2(acc[j][1], ed);
                mulf2(acc[j][2], ed); mulf2(acc[j][3], ed);
                float2 r0 = unpk(acc[j][0]), r1 = unpk(acc[j][1]);
                float2 r2 = unpk(acc[j][2]), r3 = unpk(acc[j][3]);
                float* dst = out + (size_t)pidx[chb + j] * DIM + cg * 8;
                asm volatile("red.global.add.v4.f32 [%0], {%1,%2,%3,%4};"
                             :: "l"(dst), "f"(r0.x), "f"(r0.y), "f"(r1.x), "f"(r1.y)
                             : "memory");
                asm volatile("red.global.add.v4.f32 [%0], {%1,%2,%3,%4};"
                             :: "l"(dst + 4), "f"(r2.x), "f"(r2.y), "f"(r3.x), "f"(r3.y)
                             : "memory");
            }
        }
        __syncthreads();   // protect xs/e_s/pidx before next tile's staging
    }
}

// ---------------- final normalize: out[p][j] /= (s[p][j>>4] + 1e-16) ----------------
__global__ void norm_kernel(float* __restrict__ out, int np) {
    int idx = blockIdx.x * blockDim.x + threadIdx.x;   // np*16 float4 groups
    if (idx >= np * 16) return;
    int p = idx >> 4, grp = idx & 15;
    float s = g_s[p * H + (grp >> 2)];
    float inv = 1.0f / (s + 1e-16f);
    float4 v = *(const float4*)&out[(size_t)p * DIM + grp * 4];
    v.x *= inv; v.y *= inv; v.z *= inv; v.w *= inv;
    *(float4*)&out[(size_t)p * DIM + grp * 4] = v;
}

// ---------------- launch ----------------
extern "C" void kernel_launch(void* const* d_in, const int* in_sizes, int n_in,
                              void* d_out, int out_size) {
    const float* x_child   = (const float*)d_in[0];
    const float* x_parent  = (const float*)d_in[1];
    const void*  index     = d_in[2];
    const float* edge_attr = (const float*)d_in[3];
    const float* wq        = (const float*)d_in[4];
    const float* bq        = (const float*)d_in[5];
    const float* wkv       = (const float*)d_in[6];
    const float* bkv       = (const float*)d_in[7];
    const float* wk_rpe    = (const float*)d_in[8];
    const float* bk_rpe    = (const float*)d_in[9];
    const float* wq_rpe    = (const float*)d_in[10];
    const float* bq_rpe    = (const float*)d_in[11];
    float* out = (float*)d_out;

    const int nc = in_sizes[0] / DIM;
    const int np = in_sizes[1] / DIM;

    const int XS_BYTES = XS_FLOATS * (int)sizeof(float);
    static int attr_done = 0;
    if (!attr_done) {
        cudaFuncSetAttribute(compat_kernel,
                             cudaFuncAttributeMaxDynamicSharedMemorySize, XS_BYTES);
        cudaFuncSetAttribute(vout_kernel,
                             cudaFuncAttributeMaxDynamicSharedMemorySize, XS_BYTES);
        attr_done = 1;
    }

    cudaMemsetAsync(d_out, 0, (size_t)out_size * sizeof(float));
    void* s_addr = nullptr;
    cudaGetSymbolAddress(&s_addr, g_s);
    cudaMemsetAsync(s_addr, 0, (size_t)np * H * sizeof(float));

    detect_kernel<<<1, 256>>>((const unsigned int*)index, nc);
    cvt_index_kernel<<<(nc + 255) / 256, 256>>>(index, nc);

    qp_kernel<<<208, 256>>>(x_parent, wq, bq, np);

    const int ctiles = (nc + 255) / 256;
    compat_kernel<<<296, 256, XS_BYTES>>>(x_child, edge_attr, wkv, bkv,
                                          wk_rpe, bk_rpe, wq_rpe, bq_rpe, nc, ctiles);

    const int vtiles = (nc + 255) / 256;
    vout_kernel<<<296, 256, XS_BYTES>>>(x_child, wkv, bkv, out, nc, vtiles);

    norm_kernel<<<(np * 16 + 255) / 256, 256>>>(out, np);
}

// round 11
// speedup vs baseline: 1.8231x; 1.2079x over previous
#include <cuda_runtime.h>
#include <cuda_bf16.h>
#include <cstdint>

#define NC_MAX 1000000
#define NP_MAX 100000
#define DIM 64
#define H 4
#define DQK 8
#define DH 32
#define RPE 9
#define KVW 96
#define SCALE 0.35355339059327373f  // 8^-0.5

// tcgen05 only exists on the arch-specific ('a'/'f') targets; the harness also
// compiles a plain compute_103 PTX pass which must get a fallback body.
#if defined(__CUDA_ARCH_FEAT_SM103_ALL) || defined(__CUDA_ARCH_FEAT_SM100_ALL)
#define HAS_TCGEN05 1
#else
#define HAS_TCGEN05 0
#endif

// Skewed x-tile index (compat kernel): 16B pad per 8-child group
#define XIDX(child, c) (((child) << 6) + (((child) >> 3) << 2) + (c))
#define XS_FLOATS (256 * 64 + 32 * 4)

// ---------------- packed f32x2 helpers ----------------
__device__ __forceinline__ unsigned long long pk2(float v) {
    unsigned long long r;
    asm("mov.b64 %0, {%1, %1};" : "=l"(r) : "f"(v));
    return r;
}
__device__ __forceinline__ void ffma2(unsigned long long& d, unsigned long long a,
                                      unsigned long long b) {
    asm("fma.rn.f32x2 %0, %1, %2, %0;" : "+l"(d) : "l"(a), "l"(b));
}
__device__ __forceinline__ void addf2(unsigned long long& d, unsigned long long a) {
    asm("add.rn.f32x2 %0, %0, %1;" : "+l"(d) : "l"(a));
}
__device__ __forceinline__ float2 unpk(unsigned long long v) {
    float2 r;
    asm("mov.b64 {%0, %1}, %2;" : "=f"(r.x), "=f"(r.y) : "l"(v));
    return r;
}

// ---------------- smem/tcgen05 helpers ----------------
__device__ __forceinline__ uint32_t smem_u32(const void* p) {
    uint32_t a;
    asm("{ .reg .u64 t; cvta.to.shared.u64 t, %1; cvt.u32.u64 %0, t; }"
        : "=r"(a) : "l"(p));
    return a;
}
#define SW128(b) ((b) ^ (((b) >> 3) & 0x70))

#if HAS_TCGEN05
__device__ __forceinline__ uint32_t elect1() {
    uint32_t p;
    asm volatile("{ .reg .pred p; elect.sync _|p, 0xFFFFFFFF; selp.b32 %0, 1, 0, p; }"
                 : "=r"(p));
    return p;
}
// SW128 K-major smem descriptor (version=1, SBO=64, LBO=1)
__device__ __forceinline__ uint64_t mk_desc(uint32_t addr) {
    return ((uint64_t)2 << 61) | ((uint64_t)1 << 46) | ((uint64_t)64 << 32)
         | ((uint64_t)1 << 16) | ((uint64_t)(addr >> 4) & 0x3FFF);
}

#define TCGEN05_MMA_TF32_SS(dt, ad, bd, id, en) do {                           \
    uint32_t _en = (en) ? 1u : 0u;                                             \
    asm volatile("{\n\t.reg .pred p;\n\tsetp.ne.u32 p, %5, 0;\n\t"             \
        "tcgen05.mma.cta_group::1.kind::tf32 [%0], %1, %2, %3, {%4,%4,%4,%4}, p;\n\t}" \
        :: "r"(dt), "l"(ad), "l"(bd), "r"(id), "r"(0u), "r"(_en) : "memory");  \
} while (0)

#define LDTM32(r, addr)                                                        \
    asm volatile("tcgen05.ld.sync.aligned.32x32b.x32.b32 "                     \
        "{%0,%1,%2,%3,%4,%5,%6,%7,%8,%9,%10,%11,%12,%13,%14,%15,"              \
        "%16,%17,%18,%19,%20,%21,%22,%23,%24,%25,%26,%27,%28,%29,%30,%31}, [%32];" \
        : "=r"((r)[0]),"=r"((r)[1]),"=r"((r)[2]),"=r"((r)[3]),                 \
          "=r"((r)[4]),"=r"((r)[5]),"=r"((r)[6]),"=r"((r)[7]),                 \
          "=r"((r)[8]),"=r"((r)[9]),"=r"((r)[10]),"=r"((r)[11]),               \
          "=r"((r)[12]),"=r"((r)[13]),"=r"((r)[14]),"=r"((r)[15]),             \
          "=r"((r)[16]),"=r"((r)[17]),"=r"((r)[18]),"=r"((r)[19]),             \
          "=r"((r)[20]),"=r"((r)[21]),"=r"((r)[22]),"=r"((r)[23]),             \
          "=r"((r)[24]),"=r"((r)[25]),"=r"((r)[26]),"=r"((r)[27]),             \
          "=r"((r)[28]),"=r"((r)[29]),"=r"((r)[30]),"=r"((r)[31]) : "r"(addr))

// idesc: dtype F32 (bit4), atype TF32=2 (bits7-9), btype TF32=2 (bits10-12),
// N/8 at bits17-22, M/16 at bits24-28
#define IDESC_TF32 ((1u << 4) | (2u << 7) | (2u << 10) | (8u << 17) | (8u << 24))
#endif  // HAS_TCGEN05

// ---------------- device scratch ----------------
__device__ __align__(16) float g_qp[NP_MAX * DH];
__device__ __align__(16) float g_e[NC_MAX * H];
__device__ __align__(16) float g_s[NP_MAX * H];
__device__ int g_idx[NC_MAX];
__device__ int g_is64;

// ---------------- index dtype detection ----------------
__global__ void detect_kernel(const unsigned int* __restrict__ raw, int nc) {
    __shared__ int found;
    if (threadIdx.x == 0) found = 0;
    __syncthreads();
    int limit = nc / 2; if (limit > 2048) limit = 2048;
    for (int i = threadIdx.x; i < limit; i += blockDim.x)
        if (raw[2 * i + 1] != 0u) found = 1;
    __syncthreads();
    if (threadIdx.x == 0) g_is64 = (found == 0) ? 1 : 0;
}

__global__ void cvt_index_kernel(const void* __restrict__ idxp, int nc) {
    int i = blockIdx.x * blockDim.x + threadIdx.x;
    if (i >= nc) return;
    if (g_is64) g_idx[i] = (int)((const long long*)idxp)[i];
    else        g_idx[i] = ((const int*)idxp)[i];
}

// ---------------- parent query projection ----------------
__global__ void __launch_bounds__(256, 2) qp_kernel(
    const float* __restrict__ x_parent, const float* __restrict__ wq,
    const float* __restrict__ bq, int np)
{
    const int t = threadIdx.x & 31;
    const int w = threadIdx.x >> 5;
    __shared__ __align__(16) float xs[8][64];

    float wr[64];
#pragma unroll
    for (int c = 0; c < 64; c++) wr[c] = wq[c * DH + t];
    const float b = bq[t];

    const int warps_total = gridDim.x * 8;
    for (int p = blockIdx.x * 8 + w; p < np; p += warps_total) {
        size_t base = (size_t)p * DIM;
        xs[w][t]      = x_parent[base + t];
        xs[w][t + 32] = x_parent[base + 32 + t];
        __syncwarp();
        float a0 = b, a1 = 0.f, a2 = 0.f, a3 = 0.f;
#pragma unroll
        for (int c = 0; c < 64; c += 4) {
            float4 xv = *(const float4*)&xs[w][c];
            a0 += xv.x * wr[c];
            a1 += xv.y * wr[c + 1];
            a2 += xv.z * wr[c + 2];
            a3 += xv.w * wr[c + 3];
        }
        g_qp[(size_t)p * DH + t] = ((a0 + a1) + (a2 + a3)) * SCALE;
        __syncwarp();
    }
}

// ---------------- compat (round-9 proven, unchanged) ----------------
__global__ void __launch_bounds__(256, 2) compat_kernel(
    const float* __restrict__ x_child, const float* __restrict__ edge_attr,
    const float* __restrict__ wkv, const float* __restrict__ bkv,
    const float* __restrict__ wk_rpe, const float* __restrict__ bk_rpe,
    const float* __restrict__ wq_rpe, const float* __restrict__ bq_rpe,
    int nc, int ntiles)
{
    extern __shared__ __align__(16) float xs[];
    __shared__ __align__(16) float ws[64][32];
    __shared__ __align__(16) float wkr_s[RPE][32];
    __shared__ __align__(16) float wqr_s[RPE][32];
    __shared__ __align__(16) float bk_s[32];
    __shared__ __align__(16) float bq_s[32];
    __shared__ __align__(16) float eas[256][12];
    __shared__ __align__(16) float es4[256][4];
    __shared__ int pidx[256];

    const int tid = threadIdx.x;
    const int cg = tid & 7;
    const int chb = (tid >> 3) * 8;

    for (int k = tid; k < 64 * 32; k += 256) {
        int c = k >> 5, col = k & 31;
        ws[c][col] = wkv[c * KVW + col];
    }
    for (int k = tid; k < RPE * 32; k += 256) {
        wkr_s[0][k] = wk_rpe[k];
        wqr_s[0][k] = wq_rpe[k];
    }
    if (tid < 32) {
        bk_s[tid] = bkv[tid] + bk_rpe[tid];
        bq_s[tid] = bq_rpe[tid];
    }
    __syncthreads();

    float* ks = xs;

    for (int tile = blockIdx.x; tile < ntiles; tile += gridDim.x) {
        const int i0 = tile * 256;

        {
            int i = i0 + tid;
            pidx[tid] = (i < nc) ? g_idx[i] : 0;
        }
        for (int k = tid; k < 256 * RPE; k += 256) {
            int child = k / RPE, r = k - child * RPE;
            int i = i0 + child;
            eas[child][r] = (i < nc) ? edge_attr[(size_t)i * RPE + r] : 0.f;
        }
#pragma unroll
        for (int k = 0; k < 16; k++) {
            int idx = tid + 256 * k;
            int child = idx >> 4, c4 = idx & 15;
            int i = i0 + child;
            float4 xv = make_float4(0.f, 0.f, 0.f, 0.f);
            if (i < nc) xv = *(const float4*)&x_child[(size_t)i * DIM + c4 * 4];
            *(float4*)&xs[XIDX(child, c4 * 4)] = xv;
        }
        __syncthreads();

        const int xbase = XIDX(chb, 0);
        unsigned long long acc[8][2];
#pragma unroll
        for (int j = 0; j < 8; j++) { acc[j][0] = 0ull; acc[j][1] = 0ull; }
#pragma unroll
        for (int cc = 0; cc < 64; cc += 4) {
            float4 xv[8];
#pragma unroll
            for (int j = 0; j < 8; j++)
                xv[j] = *(const float4*)&xs[xbase + j * 64 + cc];
#pragma unroll
            for (int u = 0; u < 4; u++) {
                ulonglong2 wp = *(const ulonglong2*)&ws[cc + u][cg * 4];
#pragma unroll
                for (int j = 0; j < 8; j++) {
                    unsigned long long xd = pk2(((const float*)&xv[j])[u]);
                    ffma2(acc[j][0], xd, wp.x);
                    ffma2(acc[j][1], xd, wp.y);
                }
            }
        }
#pragma unroll
        for (int r = 0; r < RPE; r++) {
            ulonglong2 wp = *(const ulonglong2*)&wkr_s[r][cg * 4];
#pragma unroll
            for (int j = 0; j < 8; j++) {
                unsigned long long xd = pk2(eas[chb + j][r]);
                ffma2(acc[j][0], xd, wp.x);
                ffma2(acc[j][1], xd, wp.y);
            }
        }
        __syncthreads();

        {
            const int col = cg * 4;
            const float b0 = bk_s[col], b1 = bk_s[col + 1];
            const float b2 = bk_s[col + 2], b3 = bk_s[col + 3];
#pragma unroll
            for (int j = 0; j < 8; j++) {
                float2 lo = unpk(acc[j][0]);
                float2 hi = unpk(acc[j][1]);
                float* kp = &ks[(chb + j) * 33 + col];
                kp[0] = lo.x + b0; kp[1] = lo.y + b1;
                kp[2] = hi.x + b2; kp[3] = hi.y + b3;
            }
        }
        __syncthreads();

#pragma unroll
        for (int uu = 0; uu < 2; uu++) {
            const int unit = tid + uu * 256;
            const int child = unit >> 1;
            const int half = unit & 1;
            const int i = i0 + child;
            if (i < nc) {
                const int p = pidx[child];
                const int col0 = half * 16;
                unsigned long long q[8];
                const unsigned long long* qpv =
                    (const unsigned long long*)&g_qp[(size_t)p * DH + col0];
                const unsigned long long* bqp =
                    (const unsigned long long*)&bq_s[col0];
#pragma unroll
                for (int j = 0; j < 8; j++) { q[j] = qpv[j]; addf2(q[j], bqp[j]); }
#pragma unroll
                for (int r = 0; r < RPE; r++) {
                    unsigned long long ed = pk2(eas[child][r]);
                    const unsigned long long* wqp =
                        (const unsigned long long*)&wqr_s[r][col0];
#pragma unroll
                    for (int j = 0; j < 8; j++) ffma2(q[j], ed, wqp[j]);
                }
                const float* krow = &ks[child * 33 + col0];
                float c0 = 0.f, c1 = 0.f;
#pragma unroll
                for (int j = 0; j < 4; j++) {
                    float2 qq = unpk(q[j]);
                    c0 += qq.x * krow[2 * j] + qq.y * krow[2 * j + 1];
                }
#pragma unroll
                for (int j = 4; j < 8; j++) {
                    float2 qq = unpk(q[j]);
                    c1 += qq.x * krow[2 * j] + qq.y * krow[2 * j + 1];
                }
                es4[child][half * 2 + 0] = __expf(c0);
                es4[child][half * 2 + 1] = __expf(c1);
            }
        }
        __syncthreads();

        {
            int i = i0 + tid;
            if (i < nc) {
                float4 e4 = *(const float4*)&es4[tid][0];
                *(float4*)&g_e[(size_t)i * H] = e4;
                asm volatile("red.global.add.v4.f32 [%0], {%1,%2,%3,%4};"
                             :: "l"(g_s + (size_t)pidx[tid] * H),
                                "f"(e4.x), "f"(e4.y), "f"(e4.z), "f"(e4.w) : "memory");
            }
        }
        __syncthreads();
    }
}

// ---------------- vout: tcgen05 tf32 MMA (sm_103a) / fp32 fallback (PTX pass) ----------------
#define VA_BYTES (128 * 64 * 4)    // 32768
#define VB_BYTES (64 * 64 * 4)     // 16384
#define VDYN_BYTES (VA_BYTES + VB_BYTES + 1024)

__device__ __forceinline__ uint32_t a_off(int child, int col) {
    uint32_t b = (uint32_t)(((child >> 3) + ((col >= 32) ? 16 : 0)) * 1024
                 + (child & 7) * 128 + (col & 31) * 4);
    return SW128(b);
}
__device__ __forceinline__ uint32_t b_off(int n, int k) {
    uint32_t b = (uint32_t)(((n >> 3) + ((k >= 32) ? 8 : 0)) * 1024
                 + (n & 7) * 128 + (k & 31) * 4);
    return SW128(b);
}

__global__ void __launch_bounds__(128, 4) vout_kernel(
    const float* __restrict__ x_child, const float* __restrict__ wkv,
    const float* __restrict__ bkv, float* __restrict__ out,
    int nc, int ntiles)
{
#if HAS_TCGEN05
    extern __shared__ __align__(16) char vdyn[];
    __shared__ __align__(16) float e_s[128][4];
    __shared__ __align__(16) float bv_s[64];
    __shared__ int pidx[128];
    __shared__ __align__(8) unsigned long long mbar_store;
    __shared__ uint32_t tmem_ptr_store;

    const int tid = threadIdx.x;
    const int wid = tid >> 5;
    const int lid = tid & 31;

    // 1024-align the A base inside the dynamic buffer
    char* base = vdyn;
    uint32_t base_u = smem_u32(base);
    uint32_t pad = (1024u - (base_u & 1023u)) & 1023u;
    char* Abuf = base + pad;
    char* Bbuf = Abuf + VA_BYTES;
    const uint32_t a_base = base_u + pad;
    const uint32_t b_base = a_base + VA_BYTES;
    const uint32_t mbar = smem_u32(&mbar_store);

    if (wid == 0) {
        asm volatile("tcgen05.alloc.cta_group::1.sync.aligned.shared::cta.b32 [%0], %1;"
                     :: "r"(smem_u32(&tmem_ptr_store)), "r"(64u) : "memory");
        asm volatile("tcgen05.relinquish_alloc_permit.cta_group::1.sync.aligned;");
    }
    if (tid == 0) {
        asm volatile("mbarrier.init.shared.b64 [%0], %1;" :: "r"(mbar), "r"(1u) : "memory");
    }
    // stage B = wv^T (row n, col k) and bias
    for (int k = tid; k < 64 * 64; k += 128) {
        int n = k >> 6, kk = k & 63;
        *(float*)(Bbuf + b_off(n, kk)) = wkv[kk * KVW + DH + n];
    }
    if (tid < 64) bv_s[tid] = bkv[DH + tid];
    __syncthreads();
    const uint32_t tmem = tmem_ptr_store;
    const uint64_t a_desc = mk_desc(a_base);
    const uint64_t b_desc = mk_desc(b_base);

    uint32_t ph = 0;

    for (int tile = blockIdx.x; tile < ntiles; tile += gridDim.x) {
        const int i0 = tile * 128;

        // stage e + pidx
#pragma unroll
        for (int k = 0; k < 4; k++) {
            int idx = tid + 128 * k;          // 0..511
            int child = idx >> 2, h = idx & 3;
            int i = i0 + child;
            float ev = 0.f; int p = 0;
            if (i < nc) { p = g_idx[i]; ev = g_e[(size_t)i * H + h]; }
            e_s[child][h] = ev;
            if (h == 0) pidx[child] = p;
        }
        // stage A (swizzled float4)
#pragma unroll
        for (int k = 0; k < 16; k++) {
            int idx = tid + 128 * k;          // 0..2047
            int child = idx >> 4, c4 = idx & 15;
            int i = i0 + child;
            float4 xv = make_float4(0.f, 0.f, 0.f, 0.f);
            if (i < nc) xv = *(const float4*)&x_child[(size_t)i * DIM + c4 * 4];
            *(float4*)(Abuf + a_off(child, c4 * 4)) = xv;
        }
        asm volatile("fence.proxy.async.shared::cta;" ::: "memory");
        __syncthreads();

        // MMA: 8 K-steps of K=8 tf32
        if (wid == 0) {
            asm volatile("tcgen05.fence::after_thread_sync;" ::: "memory");
            if (elect1()) {
#pragma unroll
                for (int s = 0; s < 8; s++) {
                    uint64_t ao = (s < 4) ? (uint64_t)(s * 2) : (uint64_t)(1024 + (s - 4) * 2);
                    uint64_t bo = (s < 4) ? (uint64_t)(s * 2) : (uint64_t)(512 + (s - 4) * 2);
                    TCGEN05_MMA_TF32_SS(tmem, a_desc + ao, b_desc + bo, IDESC_TF32, s > 0);
                }
                asm volatile(
                    "tcgen05.commit.cta_group::1.mbarrier::arrive::one.shared::cluster.b64 [%0];"
                    :: "r"(mbar) : "memory");
            }
        }

        // all warps wait for MMA completion (parity toggles per tile)
        {
            uint32_t done;
            asm volatile("{\n\t.reg .pred p;\n\t"
                "mbarrier.try_wait.parity.acquire.cta.shared::cta.b64 p, [%1], %2;\n\t"
                "selp.b32 %0, 1, 0, p;\n\t}"
                : "=r"(done) : "r"(mbar), "r"(ph) : "memory");
            if (!done) {
                asm volatile("{\n\t.reg .pred P1;\n\t"
                    "WL_%=:\n\t"
                    "mbarrier.try_wait.parity.acquire.cta.shared::cta.b64 P1, [%0], %1, 0x989680;\n\t"
                    "@P1 bra.uni WD_%=;\n\t"
                    "bra.uni WL_%=;\n\t"
                    "WD_%=:\n\t}"
                    :: "r"(mbar), "r"(ph) : "memory");
            }
        }
        ph ^= 1;
        asm volatile("tcgen05.fence::after_thread_sync;" ::: "memory");

        // read D: lane = child within warp subpartition, 64 cols
        uint32_t d[64];
        LDTM32(d, tmem);
        LDTM32(d + 32, tmem + 32);
        asm volatile("tcgen05.wait::ld.sync.aligned;" ::: "memory");

        const int child = wid * 32 + lid;
        if (i0 + child < nc) {
            const float* ep = &e_s[child][0];
            float* dst = out + (size_t)pidx[child] * DIM;
#pragma unroll
            for (int g = 0; g < 16; g++) {
                float e = ep[g >> 2];
                float r0 = (__uint_as_float(d[4 * g + 0]) + bv_s[4 * g + 0]) * e;
                float r1 = (__uint_as_float(d[4 * g + 1]) + bv_s[4 * g + 1]) * e;
                float r2 = (__uint_as_float(d[4 * g + 2]) + bv_s[4 * g + 2]) * e;
                float r3 = (__uint_as_float(d[4 * g + 3]) + bv_s[4 * g + 3]) * e;
                asm volatile("red.global.add.v4.f32 [%0], {%1,%2,%3,%4};"
                             :: "l"(dst + 4 * g), "f"(r0), "f"(r1), "f"(r2), "f"(r3)
                             : "memory");
            }
        }
        asm volatile("tcgen05.fence::before_thread_sync;" ::: "memory");
        __syncthreads();
    }

    __syncthreads();
    if (tid == 0)
        asm volatile("mbarrier.inval.shared.b64 [%0];" :: "r"(mbar) : "memory");
    __syncthreads();
    if (wid == 0)
        asm volatile("tcgen05.dealloc.cta_group::1.sync.aligned.b32 %0, %1;"
                     :: "r"(tmem), "r"(64u));
#else
    // fp32 fallback body for the non-'a' PTX compilation pass (never runs on
    // the sm_103a GPU, which loads the sm_103a cubin; exists for correctness
    // if the PTX were ever JIT'd).
    extern __shared__ __align__(16) float fsm[];   // ws[64*64]
    float* ws = fsm;
    const int tid = threadIdx.x;
    for (int k = tid; k < 64 * 64; k += 128)
        ws[k] = wkv[(k >> 6) * KVW + DH + (k & 63)];
    __syncthreads();
    for (int tile = blockIdx.x; tile < ntiles; tile += gridDim.x) {
        int i = tile * 128 + tid;
        if (i < nc) {
            int p = g_idx[i];
            float xr[64];
#pragma unroll
            for (int c = 0; c < 64; c++) xr[c] = x_child[(size_t)i * DIM + c];
            for (int j = 0; j < 64; j++) {
                float a = bkv[DH + j];
                for (int c = 0; c < 64; c++) a += xr[c] * ws[c * 64 + j];
                float e = g_e[(size_t)i * H + (j >> 4)];
                atomicAdd(out + (size_t)p * DIM + j, a * e);
            }
        }
    }
#endif
}

// ---------------- final normalize ----------------
__global__ void norm_kernel(float* __restrict__ out, int np) {
    int idx = blockIdx.x * blockDim.x + threadIdx.x;
    if (idx >= np * 16) return;
    int p = idx >> 4, grp = idx & 15;
    float s = g_s[p * H + (grp >> 2)];
    float inv = 1.0f / (s + 1e-16f);
    float4 v = *(const float4*)&out[(size_t)p * DIM + grp * 4];
    v.x *= inv; v.y *= inv; v.z *= inv; v.w *= inv;
    *(float4*)&out[(size_t)p * DIM + grp * 4] = v;
}

// ---------------- launch ----------------
extern "C" void kernel_launch(void* const* d_in, const int* in_sizes, int n_in,
                              void* d_out, int out_size) {
    const float* x_child   = (const float*)d_in[0];
    const float* x_parent  = (const float*)d_in[1];
    const void*  index     = d_in[2];
    const float* edge_attr = (const float*)d_in[3];
    const float* wq        = (const float*)d_in[4];
    const float* bq        = (const float*)d_in[5];
    const float* wkv       = (const float*)d_in[6];
    const float* bkv       = (const float*)d_in[7];
    const float* wk_rpe    = (const float*)d_in[8];
    const float* bk_rpe    = (const float*)d_in[9];
    const float* wq_rpe    = (const float*)d_in[10];
    const float* bq_rpe    = (const float*)d_in[11];
    float* out = (float*)d_out;

    const int nc = in_sizes[0] / DIM;
    const int np = in_sizes[1] / DIM;

    const int XS_BYTES = XS_FLOATS * (int)sizeof(float);
    static int attr_done = 0;
    if (!attr_done) {
        cudaFuncSetAttribute(compat_kernel,
                             cudaFuncAttributeMaxDynamicSharedMemorySize, XS_BYTES);
        cudaFuncSetAttribute(vout_kernel,
                             cudaFuncAttributeMaxDynamicSharedMemorySize, VDYN_BYTES);
        attr_done = 1;
    }

    cudaMemsetAsync(d_out, 0, (size_t)out_size * sizeof(float));
    void* s_addr = nullptr;
    cudaGetSymbolAddress(&s_addr, g_s);
    cudaMemsetAsync(s_addr, 0, (size_t)np * H * sizeof(float));

    detect_kernel<<<1, 256>>>((const unsigned int*)index, nc);
    cvt_index_kernel<<<(nc + 255) / 256, 256>>>(index, nc);

    qp_kernel<<<208, 256>>>(x_parent, wq, bq, np);

    const int ctiles = (nc + 255) / 256;
    compat_kernel<<<296, 256, XS_BYTES>>>(x_child, edge_attr, wkv, bkv,
                                          wk_rpe, bk_rpe, wq_rpe, bq_rpe, nc, ctiles);

    const int vtiles = (nc + 127) / 128;
    vout_kernel<<<592, 128, VDYN_BYTES>>>(x_child, wkv, bkv, out, nc, vtiles);

    norm_kernel<<<(np * 16 + 255) / 256, 256>>>(out, np);
}

// round 12
// speedup vs baseline: 2.0913x; 1.1471x over previous
#include <cuda_runtime.h>
#include <cuda_bf16.h>
#include <cstdint>

#define NC_MAX 1000000
#define NP_MAX 100000
#define DIM 64
#define H 4
#define DQK 8
#define DH 32
#define RPE 9
#define KVW 96
#define SCALE 0.35355339059327373f  // 8^-0.5

#if defined(__CUDA_ARCH_FEAT_SM103_ALL) || defined(__CUDA_ARCH_FEAT_SM100_ALL)
#define HAS_TCGEN05 1
#else
#define HAS_TCGEN05 0
#endif

// ---------------- smem helpers ----------------
__device__ __forceinline__ uint32_t smem_u32(const void* p) {
    uint32_t a;
    asm("{ .reg .u64 t; cvta.to.shared.u64 t, %1; cvt.u32.u64 %0, t; }"
        : "=r"(a) : "l"(p));
    return a;
}
#define SW128(b) ((b) ^ (((b) >> 3) & 0x70))

#if HAS_TCGEN05
__device__ __forceinline__ uint32_t elect1() {
    uint32_t p;
    asm volatile("{ .reg .pred p; elect.sync _|p, 0xFFFFFFFF; selp.b32 %0, 1, 0, p; }"
                 : "=r"(p));
    return p;
}
__device__ __forceinline__ uint64_t mk_desc(uint32_t addr) {
    return ((uint64_t)2 << 61) | ((uint64_t)1 << 46) | ((uint64_t)64 << 32)
         | ((uint64_t)1 << 16) | ((uint64_t)(addr >> 4) & 0x3FFF);
}
__device__ __forceinline__ float tf32_rna(float x) {
    uint32_t u;
    asm("cvt.rna.tf32.f32 %0, %1;" : "=r"(u) : "f"(x));
    return __uint_as_float(u);
}

#define TCGEN05_MMA_TF32_SS(dt, ad, bd, id, en) do {                           \
    uint32_t _en = (en) ? 1u : 0u;                                             \
    asm volatile("{\n\t.reg .pred p;\n\tsetp.ne.u32 p, %5, 0;\n\t"             \
        "tcgen05.mma.cta_group::1.kind::tf32 [%0], %1, %2, %3, {%4,%4,%4,%4}, p;\n\t}" \
        :: "r"(dt), "l"(ad), "l"(bd), "r"(id), "r"(0u), "r"(_en) : "memory");  \
} while (0)

#define LDTM32(r, addr)                                                        \
    asm volatile("tcgen05.ld.sync.aligned.32x32b.x32.b32 "                     \
        "{%0,%1,%2,%3,%4,%5,%6,%7,%8,%9,%10,%11,%12,%13,%14,%15,"              \
        "%16,%17,%18,%19,%20,%21,%22,%23,%24,%25,%26,%27,%28,%29,%30,%31}, [%32];" \
        : "=r"((r)[0]),"=r"((r)[1]),"=r"((r)[2]),"=r"((r)[3]),                 \
          "=r"((r)[4]),"=r"((r)[5]),"=r"((r)[6]),"=r"((r)[7]),                 \
          "=r"((r)[8]),"=r"((r)[9]),"=r"((r)[10]),"=r"((r)[11]),               \
          "=r"((r)[12]),"=r"((r)[13]),"=r"((r)[14]),"=r"((r)[15]),             \
          "=r"((r)[16]),"=r"((r)[17]),"=r"((r)[18]),"=r"((r)[19]),             \
          "=r"((r)[20]),"=r"((r)[21]),"=r"((r)[22]),"=r"((r)[23]),             \
          "=r"((r)[24]),"=r"((r)[25]),"=r"((r)[26]),"=r"((r)[27]),             \
          "=r"((r)[28]),"=r"((r)[29]),"=r"((r)[30]),"=r"((r)[31]) : "r"(addr))

#define MBAR_WAIT(mbar, ph) do {                                               \
    uint32_t _done;                                                            \
    asm volatile("{\n\t.reg .pred p;\n\t"                                      \
        "mbarrier.try_wait.parity.acquire.cta.shared::cta.b64 p, [%1], %2;\n\t"\
        "selp.b32 %0, 1, 0, p;\n\t}"                                           \
        : "=r"(_done) : "r"(mbar), "r"(ph) : "memory");                        \
    if (!_done) {                                                              \
        asm volatile("{\n\t.reg .pred P1;\n\t"                                 \
            "WL_%=:\n\t"                                                       \
            "mbarrier.try_wait.parity.acquire.cta.shared::cta.b64 P1, [%0], %1, 0x989680;\n\t" \
            "@P1 bra.uni WD_%=;\n\t"                                           \
            "bra.uni WL_%=;\n\t"                                               \
            "WD_%=:\n\t}"                                                      \
            :: "r"(mbar), "r"(ph) : "memory");                                 \
    }                                                                          \
} while (0)

// idesc: dtype F32, a/b TF32, M=128; N per kernel
#define IDESC_V ((1u << 4) | (2u << 7) | (2u << 10) | (8u << 17) | (8u << 24))  // N=64
#define IDESC_C ((1u << 4) | (2u << 7) | (2u << 10) | (4u << 17) | (8u << 24))  // N=32
#endif  // HAS_TCGEN05

// ---------------- device scratch ----------------
__device__ __align__(16) float g_qp[NP_MAX * DH];
__device__ __align__(16) float g_e[NC_MAX * H];
__device__ __align__(16) float g_s[NP_MAX * H];
__device__ int g_idx[NC_MAX];
__device__ int g_is64;

// ---------------- index dtype detection ----------------
__global__ void detect_kernel(const unsigned int* __restrict__ raw, int nc) {
    __shared__ int found;
    if (threadIdx.x == 0) found = 0;
    __syncthreads();
    int limit = nc / 2; if (limit > 2048) limit = 2048;
    for (int i = threadIdx.x; i < limit; i += blockDim.x)
        if (raw[2 * i + 1] != 0u) found = 1;
    __syncthreads();
    if (threadIdx.x == 0) g_is64 = (found == 0) ? 1 : 0;
}

__global__ void cvt_index_kernel(const void* __restrict__ idxp, int nc) {
    int i = blockIdx.x * blockDim.x + threadIdx.x;
    if (i >= nc) return;
    if (g_is64) g_idx[i] = (int)((const long long*)idxp)[i];
    else        g_idx[i] = ((const int*)idxp)[i];
}

// ---------------- parent query projection ----------------
__global__ void __launch_bounds__(256, 2) qp_kernel(
    const float* __restrict__ x_parent, const float* __restrict__ wq,
    const float* __restrict__ bq, int np)
{
    const int t = threadIdx.x & 31;
    const int w = threadIdx.x >> 5;
    __shared__ __align__(16) float xs[8][64];

    float wr[64];
#pragma unroll
    for (int c = 0; c < 64; c++) wr[c] = wq[c * DH + t];
    const float b = bq[t];

    const int warps_total = gridDim.x * 8;
    for (int p = blockIdx.x * 8 + w; p < np; p += warps_total) {
        size_t base = (size_t)p * DIM;
        xs[w][t]      = x_parent[base + t];
        xs[w][t + 32] = x_parent[base + 32 + t];
        __syncwarp();
        float a0 = b, a1 = 0.f, a2 = 0.f, a3 = 0.f;
#pragma unroll
        for (int c = 0; c < 64; c += 4) {
            float4 xv = *(const float4*)&xs[w][c];
            a0 += xv.x * wr[c];
            a1 += xv.y * wr[c + 1];
            a2 += xv.z * wr[c + 2];
            a3 += xv.w * wr[c + 3];
        }
        g_qp[(size_t)p * DH + t] = ((a0 + a1) + (a2 + a3)) * SCALE;
        __syncwarp();
    }
}

// ======================= compat: tcgen05 tf32 =======================
// Tile M=128 children. A = [x(64) | edge(9) | 0] K=96 (10 K-steps used of 12).
// Main MMA: D1(cols 0-31) = A @ [wk ; wk_rpe ; 0]^T.
// 2nd MMA:  D2(cols 32-63) = edge @ wq_rpe^T  (A atom-col 2, K=16).
// Epilogue per lane(=child): q = qp[p] + bq_rpe + D2 ; k = D1 + (bkv+bk_rpe);
// compat = per-head dot, e = exp, scatter.
#define CA_BYTES (128 * 96 * 4)   // 49152
#define CB_BYTES (32 * 96 * 4)    // 12288
#define CB2_BYTES (32 * 32 * 4)   // 4096
#define CDYN_BYTES (CA_BYTES + CB_BYTES + CB2_BYTES + 1024)

__device__ __forceinline__ uint32_t a_off96(int child, int c) {
    return SW128((uint32_t)(((child >> 3) + (c >> 5) * 16) * 1024
                 + (child & 7) * 128 + (c & 31) * 4));
}
__device__ __forceinline__ uint32_t b_off96(int n, int k) {
    return SW128((uint32_t)(((n >> 3) + (k >> 5) * 4) * 1024
                 + (n & 7) * 128 + (k & 31) * 4));
}
__device__ __forceinline__ uint32_t b2_off(int n, int k) {
    return SW128((uint32_t)((n >> 3) * 1024 + (n & 7) * 128 + k * 4));
}

__global__ void __launch_bounds__(128, 3) compat_kernel(
    const float* __restrict__ x_child, const float* __restrict__ edge_attr,
    const float* __restrict__ wkv, const float* __restrict__ bkv,
    const float* __restrict__ wk_rpe, const float* __restrict__ bk_rpe,
    const float* __restrict__ wq_rpe, const float* __restrict__ bq_rpe,
    int nc, int ntiles)
{
#if HAS_TCGEN05
    extern __shared__ __align__(16) char cdyn[];
    __shared__ __align__(16) float bkc[32];
    __shared__ __align__(16) float bqr[32];
    __shared__ __align__(8) unsigned long long mbar_store;
    __shared__ uint32_t tmem_ptr_store;

    const int tid = threadIdx.x;
    const int wid = tid >> 5;

    uint32_t base_u = smem_u32(cdyn);
    uint32_t pad = (1024u - (base_u & 1023u)) & 1023u;
    char* Abuf = cdyn + pad;
    char* Bbuf = Abuf + CA_BYTES;
    char* B2buf = Bbuf + CB_BYTES;
    const uint32_t a_base = base_u + pad;
    const uint32_t b_base = a_base + CA_BYTES;
    const uint32_t b2_base = b_base + CB_BYTES;
    const uint32_t mbar = smem_u32(&mbar_store);

    if (wid == 0) {
        asm volatile("tcgen05.alloc.cta_group::1.sync.aligned.shared::cta.b32 [%0], %1;"
                     :: "r"(smem_u32(&tmem_ptr_store)), "r"(64u) : "memory");
        asm volatile("tcgen05.relinquish_alloc_permit.cta_group::1.sync.aligned;");
    }
    if (tid == 0)
        asm volatile("mbarrier.init.shared.b64 [%0], %1;" :: "r"(mbar), "r"(1u) : "memory");

    // zero A+B+B2 once (A pad cols and B pad rows stay zero forever)
    for (int idx = tid; idx < (CA_BYTES + CB_BYTES + CB2_BYTES) / 4; idx += 128)
        ((float*)Abuf)[idx] = 0.f;
    __syncthreads();
    // stage B = [wk ; wk_rpe] (n-major rows, k cols)
    for (int idx = tid; idx < 32 * 73; idx += 128) {
        int n = idx / 73, k = idx - n * 73;
        float v = (k < 64) ? wkv[k * KVW + n] : wk_rpe[(k - 64) * DH + n];
        *(float*)(Bbuf + b_off96(n, k)) = v;
    }
    // stage B2 = wq_rpe^T
    for (int idx = tid; idx < 32 * RPE; idx += 128) {
        int n = idx / RPE, r = idx - n * RPE;
        *(float*)(B2buf + b2_off(n, r)) = wq_rpe[r * DH + n];
    }
    if (tid < 32) {
        bkc[tid] = bkv[tid] + bk_rpe[tid];
        bqr[tid] = bq_rpe[tid];
    }
    __syncthreads();

    const uint32_t tmem = tmem_ptr_store;
    const uint64_t a_desc = mk_desc(a_base);
    const uint64_t b_desc = mk_desc(b_base);
    const uint64_t b2_desc = mk_desc(b2_base);
    uint32_t ph = 0;

    for (int tile = blockIdx.x; tile < ntiles; tile += gridDim.x) {
        const int i0 = tile * 128;
        const int i = i0 + tid;                 // lane = child
        const int p = (i < nc) ? g_idx[i] : 0;

        // stage x (cols 0-63)
#pragma unroll
        for (int k = 0; k < 16; k++) {
            int idx = tid + 128 * k;            // 0..2047
            int child = idx >> 4, c4 = idx & 15;
            int i2 = i0 + child;
            float4 xv = make_float4(0.f, 0.f, 0.f, 0.f);
            if (i2 < nc) xv = *(const float4*)&x_child[(size_t)i2 * DIM + c4 * 4];
            *(float4*)(Abuf + a_off96(child, c4 * 4)) = xv;
        }
        // stage edge (cols 64-72)
#pragma unroll
        for (int r = 0; r < RPE; r++) {
            float v = (i < nc) ? edge_attr[(size_t)i * RPE + r] : 0.f;
            *(float*)(Abuf + a_off96(tid, 64 + r)) = v;
        }
        asm volatile("fence.proxy.async.shared::cta;" ::: "memory");
        __syncthreads();

        if (wid == 0) {
            asm volatile("tcgen05.fence::after_thread_sync;" ::: "memory");
            if (elect1()) {
                // main: 10 K-steps (k = 0..79)
#pragma unroll
                for (int s = 0; s < 10; s++) {
                    uint64_t ao = (uint64_t)((s >> 2) * 1024 + (s & 3) * 2);
                    uint64_t bo = (uint64_t)((s >> 2) * 256 + (s & 3) * 2);
                    TCGEN05_MMA_TF32_SS(tmem, a_desc + ao, b_desc + bo, IDESC_C, s > 0);
                }
                // q_rpe: 2 K-steps on A atom-col 2 (global cols 64-79)
#pragma unroll
                for (int t = 0; t < 2; t++) {
                    TCGEN05_MMA_TF32_SS(tmem + 32, a_desc + 2048 + t * 2,
                                        b2_desc + t * 2, IDESC_C, t > 0);
                }
                asm volatile(
                    "tcgen05.commit.cta_group::1.mbarrier::arrive::one.shared::cluster.b64 [%0];"
                    :: "r"(mbar) : "memory");
            }
        }
        MBAR_WAIT(mbar, ph);
        ph ^= 1;
        asm volatile("tcgen05.fence::after_thread_sync;" ::: "memory");

        uint32_t d[64];
        LDTM32(d, tmem);
        LDTM32(d + 32, tmem + 32);
        asm volatile("tcgen05.wait::ld.sync.aligned;" ::: "memory");

        if (i < nc) {
            const float* qp = &g_qp[(size_t)p * DH];
            float e4[4];
#pragma unroll
            for (int h = 0; h < 4; h++) {
                float c = 0.f;
#pragma unroll
                for (int j = 0; j < 8; j++) {
                    int col = h * 8 + j;
                    float qv = qp[col] + bqr[col] + __uint_as_float(d[32 + col]);
                    float kv = __uint_as_float(d[col]) + bkc[col];
                    c += qv * kv;
                }
                e4[h] = __expf(c);
            }
            *(float4*)&g_e[(size_t)i * H] = make_float4(e4[0], e4[1], e4[2], e4[3]);
            asm volatile("red.global.add.v4.f32 [%0], {%1,%2,%3,%4};"
                         :: "l"(g_s + (size_t)p * H),
                            "f"(e4[0]), "f"(e4[1]), "f"(e4[2]), "f"(e4[3]) : "memory");
        }
        asm volatile("tcgen05.fence::before_thread_sync;" ::: "memory");
        __syncthreads();
    }

    __syncthreads();
    if (tid == 0)
        asm volatile("mbarrier.inval.shared.b64 [%0];" :: "r"(mbar) : "memory");
    __syncthreads();
    if (wid == 0)
        asm volatile("tcgen05.dealloc.cta_group::1.sync.aligned.b32 %0, %1;"
                     :: "r"(tmem), "r"(64u));
#else
    // fallback for the plain compute_103 PTX pass (never executes on GPU)
    const int tid = threadIdx.x;
    for (int tile = blockIdx.x; tile < ntiles; tile += gridDim.x) {
        int i = tile * 128 + tid;
        if (i < nc) {
            int p = g_idx[i];
            float ea[RPE];
            for (int r = 0; r < RPE; r++) ea[r] = edge_attr[(size_t)i * RPE + r];
            float e4[4];
            for (int h = 0; h < 4; h++) {
                float c = 0.f;
                for (int j = 0; j < 8; j++) {
                    int col = h * 8 + j;
                    float kv = bkv[col] + bk_rpe[col];
                    for (int cdim = 0; cdim < 64; cdim++)
                        kv += x_child[(size_t)i * DIM + cdim] * wkv[cdim * KVW + col];
                    float qv = g_qp[(size_t)p * DH + col] + bq_rpe[col];
                    for (int r = 0; r < RPE; r++) {
                        kv += ea[r] * wk_rpe[r * DH + col];
                        qv += ea[r] * wq_rpe[r * DH + col];
                    }
                    c += qv * kv;
                }
                e4[h] = __expf(c);
            }
            *(float4*)&g_e[(size_t)i * H] = make_float4(e4[0], e4[1], e4[2], e4[3]);
            for (int h = 0; h < 4; h++) atomicAdd(g_s + (size_t)p * H + h, e4[h]);
        }
    }
#endif
}

// ======================= vout: 3xTF32 split-precision MMA =======================
#define VA_BYTES (128 * 64 * 4)    // 32768
#define VB_BYTES (64 * 64 * 4)     // 16384
#define VDYN_BYTES (2 * VA_BYTES + 2 * VB_BYTES + 1024)

__device__ __forceinline__ uint32_t a_off(int child, int col) {
    uint32_t b = (uint32_t)(((child >> 3) + ((col >= 32) ? 16 : 0)) * 1024
                 + (child & 7) * 128 + (col & 31) * 4);
    return SW128(b);
}
__device__ __forceinline__ uint32_t b_off(int n, int k) {
    uint32_t b = (uint32_t)(((n >> 3) + ((k >= 32) ? 8 : 0)) * 1024
                 + (n & 7) * 128 + (k & 31) * 4);
    return SW128(b);
}

__global__ void __launch_bounds__(256, 2) vout_kernel(
    const float* __restrict__ x_child, const float* __restrict__ wkv,
    const float* __restrict__ bkv, float* __restrict__ out,
    int nc, int ntiles)
{
#if HAS_TCGEN05
    extern __shared__ __align__(16) char vdyn[];
    __shared__ __align__(16) float bv_s[64];
    __shared__ __align__(8) unsigned long long mbar_store;
    __shared__ uint32_t tmem_ptr_store;

    const int tid = threadIdx.x;
    const int wid = tid >> 5;

    uint32_t base_u = smem_u32(vdyn);
    uint32_t pad = (1024u - (base_u & 1023u)) & 1023u;
    char* Abuf  = vdyn + pad;
    char* ALbuf = Abuf + VA_BYTES;
    char* Bbuf  = ALbuf + VA_BYTES;
    char* BLbuf = Bbuf + VB_BYTES;
    const uint32_t a_base  = base_u + pad;
    const uint32_t al_base = a_base + VA_BYTES;
    const uint32_t b_base  = al_base + VA_BYTES;
    const uint32_t bl_base = b_base + VB_BYTES;
    const uint32_t mbar = smem_u32(&mbar_store);

    if (wid == 0) {
        asm volatile("tcgen05.alloc.cta_group::1.sync.aligned.shared::cta.b32 [%0], %1;"
                     :: "r"(smem_u32(&tmem_ptr_store)), "r"(64u) : "memory");
        asm volatile("tcgen05.relinquish_alloc_permit.cta_group::1.sync.aligned;");
    }
    if (tid == 0)
        asm volatile("mbarrier.init.shared.b64 [%0], %1;" :: "r"(mbar), "r"(1u) : "memory");

    // stage B (tf32-rounded) + B_lo (residual); B[n][k] = wv[k][n]
    for (int k = tid; k < 64 * 64; k += 256) {
        int n = k >> 6, kk = k & 63;
        float w = wkv[kk * KVW + DH + n];
        float hi = tf32_rna(w);
        *(float*)(Bbuf + b_off(n, kk)) = hi;
        *(float*)(BLbuf + b_off(n, kk)) = w - hi;
    }
    if (tid < 64) bv_s[tid] = bkv[DH + tid];
    __syncthreads();

    const uint32_t tmem = tmem_ptr_store;
    const uint64_t a_desc  = mk_desc(a_base);
    const uint64_t al_desc = mk_desc(al_base);
    const uint64_t b_desc  = mk_desc(b_base);
    const uint64_t bl_desc = mk_desc(bl_base);
    uint32_t ph = 0;

    const int child = tid & 127;            // warps 0-3 and 4-7 share children
    const int colh = (tid >= 128) ? 32 : 0; // column half this thread handles

    for (int tile = blockIdx.x; tile < ntiles; tile += gridDim.x) {
        const int i0 = tile * 128;
        const int i = i0 + child;
        float4 ev4 = make_float4(0.f, 0.f, 0.f, 0.f);
        int p = 0;
        if (i < nc) { p = g_idx[i]; ev4 = *(const float4*)&g_e[(size_t)i * H]; }

        // stage A (tf32-rounded) + A_lo
#pragma unroll
        for (int k = 0; k < 8; k++) {
            int idx = tid + 256 * k;          // 0..2047
            int ch = idx >> 4, c4 = idx & 15;
            int i2 = i0 + ch;
            float4 xv = make_float4(0.f, 0.f, 0.f, 0.f);
            if (i2 < nc) xv = *(const float4*)&x_child[(size_t)i2 * DIM + c4 * 4];
            float4 hi, lo;
            hi.x = tf32_rna(xv.x); lo.x = xv.x - hi.x;
            hi.y = tf32_rna(xv.y); lo.y = xv.y - hi.y;
            hi.z = tf32_rna(xv.z); lo.z = xv.z - hi.z;
            hi.w = tf32_rna(xv.w); lo.w = xv.w - hi.w;
            uint32_t off = a_off(ch, c4 * 4);
            *(float4*)(Abuf + off) = hi;
            *(float4*)(ALbuf + off) = lo;
        }
        asm volatile("fence.proxy.async.shared::cta;" ::: "memory");
        __syncthreads();

        if (wid == 0) {
            asm volatile("tcgen05.fence::after_thread_sync;" ::: "memory");
            if (elect1()) {
#pragma unroll
                for (int pass = 0; pass < 3; pass++) {
                    uint64_t ad = (pass == 1) ? al_desc : a_desc;
                    uint64_t bd = (pass == 2) ? bl_desc : b_desc;
#pragma unroll
                    for (int s = 0; s < 8; s++) {
                        uint64_t ao = (uint64_t)((s >> 2) * 1024 + (s & 3) * 2);
                        uint64_t bo = (uint64_t)((s >> 2) * 512 + (s & 3) * 2);
                        TCGEN05_MMA_TF32_SS(tmem, ad + ao, bd + bo, IDESC_V,
                                            !(pass == 0 && s == 0));
                    }
                }
                asm volatile(
                    "tcgen05.commit.cta_group::1.mbarrier::arrive::one.shared::cluster.b64 [%0];"
                    :: "r"(mbar) : "memory");
            }
        }
        MBAR_WAIT(mbar, ph);
        ph ^= 1;
        asm volatile("tcgen05.fence::after_thread_sync;" ::: "memory");

        // warps 0-3 read cols 0-31, warps 4-7 read cols 32-63 (same rows)
        uint32_t d32[32];
        LDTM32(d32, tmem + colh);
        asm volatile("tcgen05.wait::ld.sync.aligned;" ::: "memory");

        if (i < nc) {
            float* dst = out + (size_t)p * DIM + colh;
            const float* ep = (const float*)&ev4;
#pragma unroll
            for (int g = 0; g < 8; g++) {
                int col = colh + g * 4;
                float e = ep[col >> 4];
                float r0 = (__uint_as_float(d32[4 * g + 0]) + bv_s[col + 0]) * e;
                float r1 = (__uint_as_float(d32[4 * g + 1]) + bv_s[col + 1]) * e;
                float r2 = (__uint_as_float(d32[4 * g + 2]) + bv_s[col + 2]) * e;
                float r3 = (__uint_as_float(d32[4 * g + 3]) + bv_s[col + 3]) * e;
                asm volatile("red.global.add.v4.f32 [%0], {%1,%2,%3,%4};"
                             :: "l"(dst + 4 * g), "f"(r0), "f"(r1), "f"(r2), "f"(r3)
                             : "memory");
            }
        }
        asm volatile("tcgen05.fence::before_thread_sync;" ::: "memory");
        __syncthreads();
    }

    __syncthreads();
    if (tid == 0)
        asm volatile("mbarrier.inval.shared.b64 [%0];" :: "r"(mbar) : "memory");
    __syncthreads();
    if (wid == 0)
        asm volatile("tcgen05.dealloc.cta_group::1.sync.aligned.b32 %0, %1;"
                     :: "r"(tmem), "r"(64u));
#else
    // fallback for the plain compute_103 PTX pass (never executes on GPU)
    const int tid = threadIdx.x;
    for (int tile = blockIdx.x; tile < ntiles; tile += gridDim.x) {
        int i = tile * 128 + (tid & 127);
        if (tid < 128 && i < nc) {
            int p = g_idx[i];
            for (int j = 0; j < 64; j++) {
                float a = bkv[DH + j];
                for (int c = 0; c < 64; c++)
                    a += x_child[(size_t)i * DIM + c] * wkv[c * KVW + DH + j];
                float e = g_e[(size_t)i * H + (j >> 4)];
                atomicAdd(out + (size_t)p * DIM + j, a * e);
            }
        }
    }
#endif
}

// ---------------- final normalize ----------------
__global__ void norm_kernel(float* __restrict__ out, int np) {
    int idx = blockIdx.x * blockDim.x + threadIdx.x;
    if (idx >= np * 16) return;
    int p = idx >> 4, grp = idx & 15;
    float s = g_s[p * H + (grp >> 2)];
    float inv = 1.0f / (s + 1e-16f);
    float4 v = *(const float4*)&out[(size_t)p * DIM + grp * 4];
    v.x *= inv; v.y *= inv; v.z *= inv; v.w *= inv;
    *(float4*)&out[(size_t)p * DIM + grp * 4] = v;
}

// ---------------- launch ----------------
extern "C" void kernel_launch(void* const* d_in, const int* in_sizes, int n_in,
                              void* d_out, int out_size) {
    const float* x_child   = (const float*)d_in[0];
    const float* x_parent  = (const float*)d_in[1];
    const void*  index     = d_in[2];
    const float* edge_attr = (const float*)d_in[3];
    const float* wq        = (const float*)d_in[4];
    const float* bq        = (const float*)d_in[5];
    const float* wkv       = (const float*)d_in[6];
    const float* bkv       = (const float*)d_in[7];
    const float* wk_rpe    = (const float*)d_in[8];
    const float* bk_rpe    = (const float*)d_in[9];
    const float* wq_rpe    = (const float*)d_in[10];
    const float* bq_rpe    = (const float*)d_in[11];
    float* out = (float*)d_out;

    const int nc = in_sizes[0] / DIM;
    const int np = in_sizes[1] / DIM;

    static int attr_done = 0;
    if (!attr_done) {
        cudaFuncSetAttribute(compat_kernel,
                             cudaFuncAttributeMaxDynamicSharedMemorySize, CDYN_BYTES);
        cudaFuncSetAttribute(vout_kernel,
                             cudaFuncAttributeMaxDynamicSharedMemorySize, VDYN_BYTES);
        attr_done = 1;
    }

    cudaMemsetAsync(d_out, 0, (size_t)out_size * sizeof(float));
    void* s_addr = nullptr;
    cudaGetSymbolAddress(&s_addr, g_s);
    cudaMemsetAsync(s_addr, 0, (size_t)np * H * sizeof(float));

    detect_kernel<<<1, 256>>>((const unsigned int*)index, nc);
    cvt_index_kernel<<<(nc + 255) / 256, 256>>>(index, nc);

    qp_kernel<<<208, 256>>>(x_parent, wq, bq, np);

    const int ntiles = (nc + 127) / 128;
    compat_kernel<<<444, 128, CDYN_BYTES>>>(x_child, edge_attr, wkv, bkv,
                                            wk_rpe, bk_rpe, wq_rpe, bq_rpe,
                                            nc, ntiles);

    vout_kernel<<<296, 256, VDYN_BYTES>>>(x_child, wkv, bkv, out, nc, ntiles);

    norm_kernel<<<(np * 16 + 255) / 256, 256>>>(out, np);
}

// round 13
// speedup vs baseline: 2.4436x; 1.1684x over previous
#include <cuda_runtime.h>
#include <cuda_bf16.h>
#include <cstdint>

#define NC_MAX 1000000
#define NP_MAX 100000
#define DIM 64
#define H 4
#define DQK 8
#define DH 32
#define RPE 9
#define KVW 96
#define SCALE 0.35355339059327373f  // 8^-0.5

#if defined(__CUDA_ARCH_FEAT_SM103_ALL) || defined(__CUDA_ARCH_FEAT_SM100_ALL)
#define HAS_TCGEN05 1
#else
#define HAS_TCGEN05 0
#endif

// ---------------- smem helpers ----------------
__device__ __forceinline__ uint32_t smem_u32(const void* p) {
    uint32_t a;
    asm("{ .reg .u64 t; cvta.to.shared.u64 t, %1; cvt.u32.u64 %0, t; }"
        : "=r"(a) : "l"(p));
    return a;
}
#define SW128(b) ((b) ^ (((b) >> 3) & 0x70))

#if HAS_TCGEN05
__device__ __forceinline__ uint32_t elect1() {
    uint32_t p;
    asm volatile("{ .reg .pred p; elect.sync _|p, 0xFFFFFFFF; selp.b32 %0, 1, 0, p; }"
                 : "=r"(p));
    return p;
}
__device__ __forceinline__ uint64_t mk_desc(uint32_t addr) {
    return ((uint64_t)2 << 61) | ((uint64_t)1 << 46) | ((uint64_t)64 << 32)
         | ((uint64_t)1 << 16) | ((uint64_t)(addr >> 4) & 0x3FFF);
}
__device__ __forceinline__ float tf32_rna(float x) {
    uint32_t u;
    asm("cvt.rna.tf32.f32 %0, %1;" : "=r"(u) : "f"(x));
    return __uint_as_float(u);
}

#define TCGEN05_MMA_TF32_SS(dt, ad, bd, id, en) do {                           \
    uint32_t _en = (en) ? 1u : 0u;                                             \
    asm volatile("{\n\t.reg .pred p;\n\tsetp.ne.u32 p, %5, 0;\n\t"             \
        "tcgen05.mma.cta_group::1.kind::tf32 [%0], %1, %2, %3, {%4,%4,%4,%4}, p;\n\t}" \
        :: "r"(dt), "l"(ad), "l"(bd), "r"(id), "r"(0u), "r"(_en) : "memory");  \
} while (0)

#define LDTM32(r, addr)                                                        \
    asm volatile("tcgen05.ld.sync.aligned.32x32b.x32.b32 "                     \
        "{%0,%1,%2,%3,%4,%5,%6,%7,%8,%9,%10,%11,%12,%13,%14,%15,"              \
        "%16,%17,%18,%19,%20,%21,%22,%23,%24,%25,%26,%27,%28,%29,%30,%31}, [%32];" \
        : "=r"((r)[0]),"=r"((r)[1]),"=r"((r)[2]),"=r"((r)[3]),                 \
          "=r"((r)[4]),"=r"((r)[5]),"=r"((r)[6]),"=r"((r)[7]),                 \
          "=r"((r)[8]),"=r"((r)[9]),"=r"((r)[10]),"=r"((r)[11]),               \
          "=r"((r)[12]),"=r"((r)[13]),"=r"((r)[14]),"=r"((r)[15]),             \
          "=r"((r)[16]),"=r"((r)[17]),"=r"((r)[18]),"=r"((r)[19]),             \
          "=r"((r)[20]),"=r"((r)[21]),"=r"((r)[22]),"=r"((r)[23]),             \
          "=r"((r)[24]),"=r"((r)[25]),"=r"((r)[26]),"=r"((r)[27]),             \
          "=r"((r)[28]),"=r"((r)[29]),"=r"((r)[30]),"=r"((r)[31]) : "r"(addr))

#define MBAR_WAIT(mbar, ph) do {                                               \
    uint32_t _done;                                                            \
    asm volatile("{\n\t.reg .pred p;\n\t"                                      \
        "mbarrier.try_wait.parity.acquire.cta.shared::cta.b64 p, [%1], %2;\n\t"\
        "selp.b32 %0, 1, 0, p;\n\t}"                                           \
        : "=r"(_done) : "r"(mbar), "r"(ph) : "memory");                        \
    if (!_done) {                                                              \
        asm volatile("{\n\t.reg .pred P1;\n\t"                                 \
            "WL_%=:\n\t"                                                       \
            "mbarrier.try_wait.parity.acquire.cta.shared::cta.b64 P1, [%0], %1, 0x989680;\n\t" \
            "@P1 bra.uni WD_%=;\n\t"                                           \
            "bra.uni WL_%=;\n\t"                                               \
            "WD_%=:\n\t}"                                                      \
            :: "r"(mbar), "r"(ph) : "memory");                                 \
    }                                                                          \
} while (0)

// idesc: dtype F32, a/b TF32, M=128; N=64 (vout) / N=32 (compat-k)
#define IDESC_V ((1u << 4) | (2u << 7) | (2u << 10) | (8u << 17) | (8u << 24))
#define IDESC_C ((1u << 4) | (2u << 7) | (2u << 10) | (4u << 17) | (8u << 24))
#endif  // HAS_TCGEN05

// ---------------- device scratch ----------------
__device__ __align__(16) float g_qp[NP_MAX * DH];
__device__ __align__(16) float g_s[NP_MAX * H];
__device__ int g_idx[NC_MAX];
__device__ int g_is64;

// ---------------- index dtype detection ----------------
__global__ void detect_kernel(const unsigned int* __restrict__ raw, int nc) {
    __shared__ int found;
    if (threadIdx.x == 0) found = 0;
    __syncthreads();
    int limit = nc / 2; if (limit > 2048) limit = 2048;
    for (int i = threadIdx.x; i < limit; i += blockDim.x)
        if (raw[2 * i + 1] != 0u) found = 1;
    __syncthreads();
    if (threadIdx.x == 0) g_is64 = (found == 0) ? 1 : 0;
}

__global__ void cvt_index_kernel(const void* __restrict__ idxp, int nc) {
    int i = blockIdx.x * blockDim.x + threadIdx.x;
    if (i >= nc) return;
    if (g_is64) g_idx[i] = (int)((const long long*)idxp)[i];
    else        g_idx[i] = ((const int*)idxp)[i];
}

// ---------------- parent query projection ----------------
__global__ void __launch_bounds__(256, 2) qp_kernel(
    const float* __restrict__ x_parent, const float* __restrict__ wq,
    const float* __restrict__ bq, int np)
{
    const int t = threadIdx.x & 31;
    const int w = threadIdx.x >> 5;
    __shared__ __align__(16) float xs[8][64];

    float wr[64];
#pragma unroll
    for (int c = 0; c < 64; c++) wr[c] = wq[c * DH + t];
    const float b = bq[t];

    const int warps_total = gridDim.x * 8;
    for (int p = blockIdx.x * 8 + w; p < np; p += warps_total) {
        size_t base = (size_t)p * DIM;
        xs[w][t]      = x_parent[base + t];
        xs[w][t + 32] = x_parent[base + 32 + t];
        __syncwarp();
        float a0 = b, a1 = 0.f, a2 = 0.f, a3 = 0.f;
#pragma unroll
        for (int c = 0; c < 64; c += 4) {
            float4 xv = *(const float4*)&xs[w][c];
            a0 += xv.x * wr[c];
            a1 += xv.y * wr[c + 1];
            a2 += xv.z * wr[c + 2];
            a3 += xv.w * wr[c + 3];
        }
        g_qp[(size_t)p * DH + t] = ((a0 + a1) + (a2 + a3)) * SCALE;
        __syncwarp();
    }
}

// ======================= fused: K-MMA + e-epilogue + V-MMA + scatter =======================
// Tile M=128 children, 128 threads (thread = child). One staging of x feeds:
//  - compat K-GEMM: D(cols 0-31)  = Ah @ Bk^T     (tf32, 8 K-steps)
//  - vout 3xTF32:   D(cols 32-95) = Ah@Bvh + Al@Bvh + Ah@Bvl
// All 32 dispatches under ONE mbar commit. Epilogue: k from D + RPE-fma,
// q from prefetched g_qp + RPE-fma, e = exp(q.k per head) -> g_s atomic;
// v = (D_v + bv) * e -> unnormalized out atomic. norm_kernel divides at end.
#define AH_BYTES (128 * 64 * 4)   // 32768
#define AL_BYTES (128 * 64 * 4)   // 32768
#define BK_BYTES (32 * 64 * 4)    // 8192
#define BV_BYTES (64 * 64 * 4)    // 16384
#define FDYN_BYTES (AH_BYTES + AL_BYTES + BK_BYTES + 2 * BV_BYTES + 1024)

__device__ __forceinline__ uint32_t a_off(int child, int col) {
    return SW128((uint32_t)(((child >> 3) + ((col >= 32) ? 16 : 0)) * 1024
                 + (child & 7) * 128 + (col & 31) * 4));
}
__device__ __forceinline__ uint32_t bk_off(int n, int k) {   // 32 rows
    return SW128((uint32_t)(((n >> 3) + (k >> 5) * 4) * 1024
                 + (n & 7) * 128 + (k & 31) * 4));
}
__device__ __forceinline__ uint32_t bv_off(int n, int k) {   // 64 rows
    return SW128((uint32_t)(((n >> 3) + (k >> 5) * 8) * 1024
                 + (n & 7) * 128 + (k & 31) * 4));
}

__global__ void __launch_bounds__(128) fused_kernel(
    const float* __restrict__ x_child, const float* __restrict__ edge_attr,
    const float* __restrict__ wkv, const float* __restrict__ bkv,
    const float* __restrict__ wk_rpe, const float* __restrict__ bk_rpe,
    const float* __restrict__ wq_rpe, const float* __restrict__ bq_rpe,
    float* __restrict__ out, int nc, int ntiles)
{
#if HAS_TCGEN05
    extern __shared__ __align__(16) char fdyn[];
    __shared__ __align__(16) float wkr_s[RPE][32];
    __shared__ __align__(16) float wqr_s[RPE][32];
    __shared__ __align__(16) float bkc[32];
    __shared__ __align__(16) float bqr[32];
    __shared__ __align__(16) float bv_s[64];
    __shared__ __align__(8) unsigned long long mbar_store;
    __shared__ uint32_t tmem_ptr_store;

    const int tid = threadIdx.x;
    const int wid = tid >> 5;

    uint32_t base_u = smem_u32(fdyn);
    uint32_t pad = (1024u - (base_u & 1023u)) & 1023u;
    char* Ah  = fdyn + pad;
    char* Al  = Ah + AH_BYTES;
    char* Bk  = Al + AL_BYTES;
    char* Bvh = Bk + BK_BYTES;
    char* Bvl = Bvh + BV_BYTES;
    const uint32_t ah_base  = base_u + pad;
    const uint32_t al_base  = ah_base + AH_BYTES;
    const uint32_t bk_base  = al_base + AL_BYTES;
    const uint32_t bvh_base = bk_base + BK_BYTES;
    const uint32_t bvl_base = bvh_base + BV_BYTES;
    const uint32_t mbar = smem_u32(&mbar_store);

    if (wid == 0) {
        asm volatile("tcgen05.alloc.cta_group::1.sync.aligned.shared::cta.b32 [%0], %1;"
                     :: "r"(smem_u32(&tmem_ptr_store)), "r"(128u) : "memory");
        asm volatile("tcgen05.relinquish_alloc_permit.cta_group::1.sync.aligned;");
    }
    if (tid == 0)
        asm volatile("mbarrier.init.shared.b64 [%0], %1;" :: "r"(mbar), "r"(1u) : "memory");

    // one-time weight staging
    for (int idx = tid; idx < 32 * 64; idx += 128) {        // Bk[n][k] = wk[k][n]
        int n = idx >> 6, k = idx & 63;
        *(float*)(Bk + bk_off(n, k)) = wkv[k * KVW + n];
    }
    for (int idx = tid; idx < 64 * 64; idx += 128) {        // Bv hi/lo
        int n = idx >> 6, k = idx & 63;
        float w = wkv[k * KVW + DH + n];
        float hi = tf32_rna(w);
        *(float*)(Bvh + bv_off(n, k)) = hi;
        *(float*)(Bvl + bv_off(n, k)) = w - hi;
    }
    for (int idx = tid; idx < RPE * 32; idx += 128) {
        wkr_s[0][idx] = wk_rpe[idx];
        wqr_s[0][idx] = wq_rpe[idx];
    }
    if (tid < 32) {
        bkc[tid] = bkv[tid] + bk_rpe[tid];
        bqr[tid] = bq_rpe[tid];
    }
    if (tid < 64) bv_s[tid] = bkv[DH + tid];
    __syncthreads();

    const uint32_t tmem = tmem_ptr_store;
    const uint64_t ah_d  = mk_desc(ah_base);
    const uint64_t al_d  = mk_desc(al_base);
    const uint64_t bk_d  = mk_desc(bk_base);
    const uint64_t bvh_d = mk_desc(bvh_base);
    const uint64_t bvl_d = mk_desc(bvl_base);
    uint32_t ph = 0;

    for (int tile = blockIdx.x; tile < ntiles; tile += gridDim.x) {
        const int i0 = tile * 128;
        const int i = i0 + tid;                 // this thread's child
        const bool live = (i < nc);
        const int p = live ? g_idx[i] : 0;

        // prefetch gathers early (hide DRAM latency under staging + MMA)
        float ea[RPE];
#pragma unroll
        for (int r = 0; r < RPE; r++)
            ea[r] = live ? edge_attr[(size_t)i * RPE + r] : 0.f;
        float qpr[32];
        {
            const float4* qv = (const float4*)&g_qp[(size_t)p * DH];
#pragma unroll
            for (int u = 0; u < 8; u++) {
                float4 v = live ? qv[u] : make_float4(0.f, 0.f, 0.f, 0.f);
                qpr[u * 4 + 0] = v.x; qpr[u * 4 + 1] = v.y;
                qpr[u * 4 + 2] = v.z; qpr[u * 4 + 3] = v.w;
            }
        }

        // stage x: hi (rna) + lo (residual)
#pragma unroll
        for (int k = 0; k < 16; k++) {
            int idx = tid + 128 * k;            // 0..2047
            int ch = idx >> 4, c4 = idx & 15;
            int i2 = i0 + ch;
            float4 xv = make_float4(0.f, 0.f, 0.f, 0.f);
            if (i2 < nc) xv = *(const float4*)&x_child[(size_t)i2 * DIM + c4 * 4];
            float4 hi, lo;
            hi.x = tf32_rna(xv.x); lo.x = xv.x - hi.x;
            hi.y = tf32_rna(xv.y); lo.y = xv.y - hi.y;
            hi.z = tf32_rna(xv.z); lo.z = xv.z - hi.z;
            hi.w = tf32_rna(xv.w); lo.w = xv.w - hi.w;
            uint32_t off = a_off(ch, c4 * 4);
            *(float4*)(Ah + off) = hi;
            *(float4*)(Al + off) = lo;
        }
        asm volatile("fence.proxy.async.shared::cta;" ::: "memory");
        __syncthreads();

        // ALL MMAs under one commit: compat K (D cols 0-31) + vout 3-pass (D cols 32-95)
        if (wid == 0) {
            asm volatile("tcgen05.fence::after_thread_sync;" ::: "memory");
            if (elect1()) {
#pragma unroll
                for (int s = 0; s < 8; s++) {
                    uint64_t ao = (uint64_t)((s >> 2) * 1024 + (s & 3) * 2);
                    uint64_t bo = (uint64_t)((s >> 2) * 256 + (s & 3) * 2);
                    TCGEN05_MMA_TF32_SS(tmem, ah_d + ao, bk_d + bo, IDESC_C, s > 0);
                }
#pragma unroll
                for (int pass = 0; pass < 3; pass++) {
                    uint64_t ad = (pass == 1) ? al_d : ah_d;
                    uint64_t bd = (pass == 2) ? bvl_d : bvh_d;
#pragma unroll
                    for (int s = 0; s < 8; s++) {
                        uint64_t ao = (uint64_t)((s >> 2) * 1024 + (s & 3) * 2);
                        uint64_t bo = (uint64_t)((s >> 2) * 512 + (s & 3) * 2);
                        TCGEN05_MMA_TF32_SS(tmem + 32, ad + ao, bd + bo, IDESC_V,
                                            !(pass == 0 && s == 0));
                    }
                }
                asm volatile(
                    "tcgen05.commit.cta_group::1.mbarrier::arrive::one.shared::cluster.b64 [%0];"
                    :: "r"(mbar) : "memory");
            }
        }
        MBAR_WAIT(mbar, ph);
        ph ^= 1;
        asm volatile("tcgen05.fence::after_thread_sync;" ::: "memory");

        // read all D columns (issue all LDTMs, single wait)
        uint32_t dk[32], dv[64];
        LDTM32(dk, tmem);
        LDTM32(dv, tmem + 32);
        LDTM32(dv + 32, tmem + 64);
        asm volatile("tcgen05.wait::ld.sync.aligned;" ::: "memory");

        if (live) {
            // epilogue-e: k = D_k + bias + edge@wk_rpe ; q = qp + bias + edge@wq_rpe
            float e4[4];
#pragma unroll
            for (int h = 0; h < 4; h++) {
                float c = 0.f;
#pragma unroll
                for (int j = 0; j < 8; j++) {
                    int col = h * 8 + j;
                    float kv = __uint_as_float(dk[col]) + bkc[col];
                    float qv = qpr[col] + bqr[col];
#pragma unroll
                    for (int r = 0; r < RPE; r++) {
                        kv += ea[r] * wkr_s[r][col];
                        qv += ea[r] * wqr_s[r][col];
                    }
                    c += qv * kv;
                }
                e4[h] = __expf(c);
            }
            asm volatile("red.global.add.v4.f32 [%0], {%1,%2,%3,%4};"
                         :: "l"(g_s + (size_t)p * H),
                            "f"(e4[0]), "f"(e4[1]), "f"(e4[2]), "f"(e4[3]) : "memory");

            // v-scatter (unnormalized)
            float* dst = out + (size_t)p * DIM;
#pragma unroll
            for (int g = 0; g < 16; g++) {
                int col = g * 4;
                float e = e4[g >> 2];
                float r0 = (__uint_as_float(dv[col + 0]) + bv_s[col + 0]) * e;
                float r1 = (__uint_as_float(dv[col + 1]) + bv_s[col + 1]) * e;
                float r2 = (__uint_as_float(dv[col + 2]) + bv_s[col + 2]) * e;
                float r3 = (__uint_as_float(dv[col + 3]) + bv_s[col + 3]) * e;
                asm volatile("red.global.add.v4.f32 [%0], {%1,%2,%3,%4};"
                             :: "l"(dst + col), "f"(r0), "f"(r1), "f"(r2), "f"(r3)
                             : "memory");
            }
        }
        asm volatile("tcgen05.fence::before_thread_sync;" ::: "memory");
        __syncthreads();   // D consumed, A buffers free for next tile
    }

    __syncthreads();
    if (tid == 0)
        asm volatile("mbarrier.inval.shared.b64 [%0];" :: "r"(mbar) : "memory");
    __syncthreads();
    if (wid == 0)
        asm volatile("tcgen05.dealloc.cta_group::1.sync.aligned.b32 %0, %1;"
                     :: "r"(tmem), "r"(128u));
#else
    // fallback for the plain compute_103 PTX pass (never executes on the GPU,
    // which loads the sm_103a cubin)
    const int tid = threadIdx.x;
    for (int tile = blockIdx.x; tile < ntiles; tile += gridDim.x) {
        int i = tile * 128 + tid;
        if (i < nc) {
            int p = g_idx[i];
            float ea[RPE];
            for (int r = 0; r < RPE; r++) ea[r] = edge_attr[(size_t)i * RPE + r];
            float e4[4];
            for (int h = 0; h < 4; h++) {
                float c = 0.f;
                for (int j = 0; j < 8; j++) {
                    int col = h * 8 + j;
                    float kv = bkv[col] + bk_rpe[col];
                    for (int cd = 0; cd < 64; cd++)
                        kv += x_child[(size_t)i * DIM + cd] * wkv[cd * KVW + col];
                    float qv = g_qp[(size_t)p * DH + col] + bq_rpe[col];
                    for (int r = 0; r < RPE; r++) {
                        kv += ea[r] * wk_rpe[r * DH + col];
                        qv += ea[r] * wq_rpe[r * DH + col];
                    }
                    c += qv * kv;
                }
                e4[h] = __expf(c);
            }
            for (int h = 0; h < 4; h++) atomicAdd(g_s + (size_t)p * H + h, e4[h]);
            for (int j = 0; j < 64; j++) {
                float a = bkv[DH + j];
                for (int cd = 0; cd < 64; cd++)
                    a += x_child[(size_t)i * DIM + cd] * wkv[cd * KVW + DH + j];
                atomicAdd(out + (size_t)p * DIM + j, a * e4[j >> 4]);
            }
        }
    }
#endif
}

// ---------------- final normalize ----------------
__global__ void norm_kernel(float* __restrict__ out, int np) {
    int idx = blockIdx.x * blockDim.x + threadIdx.x;
    if (idx >= np * 16) return;
    int p = idx >> 4, grp = idx & 15;
    float s = g_s[p * H + (grp >> 2)];
    float inv = 1.0f / (s + 1e-16f);
    float4 v = *(const float4*)&out[(size_t)p * DIM + grp * 4];
    v.x *= inv; v.y *= inv; v.z *= inv; v.w *= inv;
    *(float4*)&out[(size_t)p * DIM + grp * 4] = v;
}

// ---------------- launch ----------------
extern "C" void kernel_launch(void* const* d_in, const int* in_sizes, int n_in,
                              void* d_out, int out_size) {
    const float* x_child   = (const float*)d_in[0];
    const float* x_parent  = (const float*)d_in[1];
    const void*  index     = d_in[2];
    const float* edge_attr = (const float*)d_in[3];
    const float* wq        = (const float*)d_in[4];
    const float* bq        = (const float*)d_in[5];
    const float* wkv       = (const float*)d_in[6];
    const float* bkv       = (const float*)d_in[7];
    const float* wk_rpe    = (const float*)d_in[8];
    const float* bk_rpe    = (const float*)d_in[9];
    const float* wq_rpe    = (const float*)d_in[10];
    const float* bq_rpe    = (const float*)d_in[11];
    float* out = (float*)d_out;

    const int nc = in_sizes[0] / DIM;
    const int np = in_sizes[1] / DIM;

    static int attr_done = 0;
    if (!attr_done) {
        cudaFuncSetAttribute(fused_kernel,
                             cudaFuncAttributeMaxDynamicSharedMemorySize, FDYN_BYTES);
        attr_done = 1;
    }

    cudaMemsetAsync(d_out, 0, (size_t)out_size * sizeof(float));
    void* s_addr = nullptr;
    cudaGetSymbolAddress(&s_addr, g_s);
    cudaMemsetAsync(s_addr, 0, (size_t)np * H * sizeof(float));

    detect_kernel<<<1, 256>>>((const unsigned int*)index, nc);
    cvt_index_kernel<<<(nc + 255) / 256, 256>>>(index, nc);

    qp_kernel<<<208, 256>>>(x_parent, wq, bq, np);

    const int ntiles = (nc + 127) / 128;
    fused_kernel<<<296, 128, FDYN_BYTES>>>(x_child, edge_attr, wkv, bkv,
                                           wk_rpe, bk_rpe, wq_rpe, bq_rpe,
                                           out, nc, ntiles);

    norm_kernel<<<(np * 16 + 255) / 256, 256>>>(out, np);
}